// round 5
// baseline (speedup 1.0000x reference)
#include <cuda_runtime.h>
#include <math.h>

// ---------------- problem constants ----------------
#define NN   30000
#define EE   480000
#define DIN  768
#define DH   256    // HID
#define DOUT 128    // OUT
#define NHEAD 4
#define NCLS 3

// ---------------- scratch (static device memory; no allocations) ----------------
__device__ float    g_Wh   [(size_t)NN * (NHEAD * DH)];   // Wh all heads, [N,1024]
__device__ float    g_xnew [(size_t)NN * (NHEAD * DH)];   // x_new concat, [N,1024]
__device__ float    g_s1   [NHEAD * NN];
__device__ float    g_s2   [NHEAD * NN];
__device__ float    g_logits [(size_t)NHEAD * EE];
__device__ float    g_logits2[EE];
__device__ float    g_hbuf [(size_t)NN * 128];            // evidence hidden (reused)
__device__ float    g_evsum[NN * NCLS];
__device__ float    g_h1   [(size_t)NN * DH];
__device__ float    g_Wh2  [(size_t)NN * DOUT];
__device__ float    g_s1b  [NN];
__device__ float    g_s2b  [NN];
__device__ float    g_xnew2[(size_t)NN * DOUT];
__device__ float    g_x2   [(size_t)NN * DOUT];
__device__ unsigned g_maxenc[8];
__device__ double   g_sumexp[8];
__device__ float    g_invS  [8];

// ---------------- helpers ----------------
__device__ __forceinline__ unsigned fenc(float f) {
    unsigned u = __float_as_uint(f);
    return (u & 0x80000000u) ? ~u : (u | 0x80000000u);
}
__device__ __forceinline__ float fdec(unsigned u) {
    return (u & 0x80000000u) ? __uint_as_float(u & 0x7fffffffu) : __uint_as_float(~u);
}
__device__ __forceinline__ float wsumf(float v) {
#pragma unroll
    for (int o = 16; o > 0; o >>= 1) v += __shfl_xor_sync(0xffffffffu, v, o);
    return v;
}
__device__ __forceinline__ float softplusf(float x) {
    return fmaxf(x, 0.f) + log1pf(expf(-fabsf(x)));
}
__device__ __forceinline__ float eluf(float x) {
    return x > 0.f ? x : expm1f(x);
}

// ---------------- init: zero accumulators + softmax scalars ----------------
__global__ void k_init() {
    size_t i = (size_t)blockIdx.x * blockDim.x + threadIdx.x;
    size_t stride = (size_t)gridDim.x * blockDim.x;
    const size_t n1 = (size_t)NN * (NHEAD * DH);
    for (size_t j = i; j < n1; j += stride) g_xnew[j] = 0.f;
    const size_t n2 = (size_t)NN * DOUT;
    for (size_t j = i; j < n2; j += stride) g_xnew2[j] = 0.f;
    const size_t n3 = (size_t)NN * NCLS;
    for (size_t j = i; j < n3; j += stride) g_evsum[j] = 0.f;
    if (i < 8) { g_maxenc[i] = 0u; g_sumexp[i] = 0.0; g_invS[i] = 0.f; }
}

// ---------------- generic tiled fp32 SGEMM ----------------
// C[M,N] = A[M,K] @ B[K,N]  (row-major, lda/ldb/ldc element strides)
// B may be "head-blocked": column n lives in head n/headSize at
//   B + (n/headSize)*headStrideB, local column n%headSize, row stride ldb.
// EPI: 0 = +bias, store; 1 = relu(+bias); 2 = +bias +addend (residual), store.
#define BM 128
#define BN 128
#define BKK 16

template <int EPI>
__global__ __launch_bounds__(256, 2)
void k_sgemm(const float* __restrict__ A, int lda,
             const float* __restrict__ B, int ldb,
             float* __restrict__ C, int ldc,
             const float* __restrict__ bias,
             const float* __restrict__ addend, int ldadd,
             int M, int N, int K, int headSize, size_t headStrideB)
{
    __shared__ float As[BKK][BM + 4];   // pad 4 -> 132 floats/row (16B aligned, low-conflict)
    __shared__ float Bs[BKK][BN];

    const int tid = threadIdx.x;
    const int m0 = blockIdx.y * BM;
    const int n0 = blockIdx.x * BN;

    const int head = n0 / headSize;
    const float* __restrict__ Bp = B + (size_t)head * headStrideB;
    const int nloc0 = n0 - head * headSize;

    const int tm = tid >> 4;   // 0..15
    const int tn = tid & 15;   // 0..15

    float acc[8][8];
#pragma unroll
    for (int i = 0; i < 8; i++)
#pragma unroll
        for (int j = 0; j < 8; j++) acc[i][j] = 0.f;

    for (int k0 = 0; k0 < K; k0 += BKK) {
        // load A tile (128x16), transposed into As[k][m]
#pragma unroll
        for (int i = 0; i < 8; i++) {
            int e = tid + 256 * i;
            int m = e >> 4, kk = e & 15;
            int gm = m0 + m;
            float v = 0.f;
            if (gm < M) v = A[(size_t)gm * lda + (k0 + kk)];
            As[kk][m] = v;
        }
        // load B tile (16x128), 2 float4 per thread
#pragma unroll
        for (int i = 0; i < 2; i++) {
            int f = tid + 256 * i;
            int kk = f >> 5;
            int nb = (f & 31) << 2;
            int gn = n0 + nb;
            float4 v = make_float4(0.f, 0.f, 0.f, 0.f);
            const float* bp = &Bp[(size_t)(k0 + kk) * ldb + (nloc0 + nb)];
            if (gn + 3 < N) {
                v = *(const float4*)bp;
            } else {
                if (gn     < N) v.x = bp[0];
                if (gn + 1 < N) v.y = bp[1];
                if (gn + 2 < N) v.z = bp[2];
            }
            *(float4*)&Bs[kk][nb] = v;
        }
        __syncthreads();

#pragma unroll
        for (int kk = 0; kk < BKK; kk++) {
            float a[8], b[8];
#pragma unroll
            for (int i = 0; i < 8; i++) a[i] = As[kk][tm * 8 + i];
#pragma unroll
            for (int j = 0; j < 8; j++) b[j] = Bs[kk][tn * 8 + j];
#pragma unroll
            for (int i = 0; i < 8; i++)
#pragma unroll
                for (int j = 0; j < 8; j++) acc[i][j] = fmaf(a[i], b[j], acc[i][j]);
        }
        __syncthreads();
    }

#pragma unroll
    for (int i = 0; i < 8; i++) {
        int gm = m0 + tm * 8 + i;
        if (gm < M) {
#pragma unroll
            for (int j = 0; j < 8; j++) {
                int gn = n0 + tn * 8 + j;
                if (gn < N) {
                    float v = acc[i][j];
                    if (bias) v += bias[gn];
                    if (EPI == 1) v = fmaxf(v, 0.f);
                    if (EPI == 2) v += addend[(size_t)gm * ldadd + gn];
                    C[(size_t)gm * ldc + gn] = v;
                }
            }
        }
    }
}

// ---------------- per-node attention projections: s1 = Wh.a[:F], s2 = Wh.a[F:] ----------------
__global__ void k_s1s2(const float* __restrict__ Wh, int ld, int F, int nh,
                       const float* __restrict__ a, int aStride,
                       float* __restrict__ s1, float* __restrict__ s2, int N)
{
    int gw = (blockIdx.x * blockDim.x + threadIdx.x) >> 5;
    int lane = threadIdx.x & 31;
    if (gw >= N * nh) return;
    int node = gw / nh;
    int h = gw - node * nh;
    const float* wr = &Wh[(size_t)node * ld + h * F];
    const float* ah = &a[(size_t)h * aStride];
    float p1 = 0.f, p2 = 0.f;
    for (int j = lane; j < F; j += 32) {
        float x = wr[j];
        p1 = fmaf(x, ah[j], p1);
        p2 = fmaf(x, ah[F + j], p2);
    }
    p1 = wsumf(p1);
    p2 = wsumf(p2);
    if (lane == 0) { s1[(size_t)h * N + node] = p1; s2[(size_t)h * N + node] = p2; }
}

// ---------------- logits + leaky_relu + global max (block-reduced) ----------------
template <int NH>
__global__ void k_logits(const int* __restrict__ src, const int* __restrict__ tgt,
                         const float* __restrict__ s1, const float* __restrict__ s2,
                         float* __restrict__ logits, int E, int N, int slot0)
{
    int e = blockIdx.x * blockDim.x + threadIdx.x;
    bool ok = (e < E);
    int s = 0, t = 0;
    if (ok) { s = src[e]; t = tgt[e]; }
    float lv[NH];
#pragma unroll
    for (int h = 0; h < NH; h++) {
        float l = -3.0e38f;
        if (ok) {
            l = s1[(size_t)h * N + s] + s2[(size_t)h * N + t];
            l = (l > 0.f) ? l : 0.2f * l;
            logits[(size_t)h * E + e] = l;
        }
        lv[h] = l;
    }
    __shared__ float red[256];
#pragma unroll
    for (int h = 0; h < NH; h++) {
        red[threadIdx.x] = lv[h];
        __syncthreads();
        for (int sft = 128; sft > 0; sft >>= 1) {
            if (threadIdx.x < sft) red[threadIdx.x] = fmaxf(red[threadIdx.x], red[threadIdx.x + sft]);
            __syncthreads();
        }
        if (threadIdx.x == 0) atomicMax(&g_maxenc[slot0 + h], fenc(red[0]));
        __syncthreads();
    }
}

// ---------------- exp(l - max), in-place, plus global sum (double) ----------------
template <int NH>
__global__ void k_sumexp(float* __restrict__ logits, int E, int slot0)
{
    int e = blockIdx.x * blockDim.x + threadIdx.x;
    float sv[NH];
#pragma unroll
    for (int h = 0; h < NH; h++) {
        float w = 0.f;
        if (e < E) {
            float M = fdec(g_maxenc[slot0 + h]);
            w = expf(logits[(size_t)h * E + e] - M);
            logits[(size_t)h * E + e] = w;
        }
        sv[h] = w;
    }
    __shared__ float red[256];
#pragma unroll
    for (int h = 0; h < NH; h++) {
        red[threadIdx.x] = sv[h];
        __syncthreads();
        for (int sft = 128; sft > 0; sft >>= 1) {
            if (threadIdx.x < sft) red[threadIdx.x] += red[threadIdx.x + sft];
            __syncthreads();
        }
        if (threadIdx.x == 0) atomicAdd(&g_sumexp[slot0 + h], (double)red[0]);
        __syncthreads();
    }
}

__global__ void k_finalize(int slot0, int n)
{
    int i = threadIdx.x;
    if (i < n) g_invS[slot0 + i] = (float)(1.0 / g_sumexp[slot0 + i]);
}

// ---------------- scatter: x_new[tgt] += alpha * Wh[src]  (warp per edge) ----------------
template <int NH, int F>
__global__ void k_scatter(const int* __restrict__ src, const int* __restrict__ tgt,
                          const float* __restrict__ w,
                          const float* __restrict__ Wh, int ldWh,
                          float* __restrict__ xnew, int ldx, int E, int slot0)
{
    int gw = (blockIdx.x * blockDim.x + threadIdx.x) >> 5;
    int lane = threadIdx.x & 31;
    if (gw >= E) return;
    int s = src[gw], t = tgt[gw];
#pragma unroll
    for (int h = 0; h < NH; h++) {
        float c = w[(size_t)h * E + gw] * g_invS[slot0 + h];
        const float* wrow = &Wh[(size_t)s * ldWh + h * F];
        float*       xrow = &xnew[(size_t)t * ldx + h * F];
#pragma unroll
        for (int j0 = 0; j0 < F; j0 += 128) {
            int j = j0 + lane * 4;
            float4 v = *(const float4*)&wrow[j];
            atomicAdd(&xrow[j + 0], c * v.x);
            atomicAdd(&xrow[j + 1], c * v.y);
            atomicAdd(&xrow[j + 2], c * v.z);
            atomicAdd(&xrow[j + 3], c * v.w);
        }
    }
}

// ---------------- evidence head: softplus(h @ w2 + b2) + 1 ----------------
// FINAL=false: g_evsum[n,c] += e_c ; FINAL=true: out[n,c] = (g_evsum*0.25 + e_c)*0.5
template <bool FINAL>
__global__ void k_evidence(const float* __restrict__ hbuf, int Kh,
                           const float* __restrict__ w2, const float* __restrict__ b2,
                           float* __restrict__ out, int N)
{
    int gw = (blockIdx.x * blockDim.x + threadIdx.x) >> 5;
    int lane = threadIdx.x & 31;
    if (gw >= N) return;
    float a0 = 0.f, a1 = 0.f, a2 = 0.f;
    const float* hr = &hbuf[(size_t)gw * Kh];
    for (int k = lane; k < Kh; k += 32) {
        float v = hr[k];
        a0 = fmaf(v, w2[k * 3 + 0], a0);
        a1 = fmaf(v, w2[k * 3 + 1], a1);
        a2 = fmaf(v, w2[k * 3 + 2], a2);
    }
    a0 = wsumf(a0); a1 = wsumf(a1); a2 = wsumf(a2);
    if (lane == 0) {
        float e0 = softplusf(a0 + b2[0]) + 1.f;
        float e1 = softplusf(a1 + b2[1]) + 1.f;
        float e2 = softplusf(a2 + b2[2]) + 1.f;
        if (FINAL) {
            out[(size_t)gw * 3 + 0] = (g_evsum[gw * 3 + 0] * 0.25f + e0) * 0.5f;
            out[(size_t)gw * 3 + 1] = (g_evsum[gw * 3 + 1] * 0.25f + e1) * 0.5f;
            out[(size_t)gw * 3 + 2] = (g_evsum[gw * 3 + 2] * 0.25f + e2) * 0.5f;
        } else {
            g_evsum[gw * 3 + 0] += e0;
            g_evsum[gw * 3 + 1] += e1;
            g_evsum[gw * 3 + 2] += e2;
        }
    }
}

// ---------------- LayerNorm (population var, eps=1e-5) + ELU, warp per row ----------------
template <int F>
__global__ void k_ln_elu(const float* __restrict__ in, float* __restrict__ out,
                         const float* __restrict__ gam, const float* __restrict__ bet, int N)
{
    int gw = (blockIdx.x * blockDim.x + threadIdx.x) >> 5;
    int lane = threadIdx.x & 31;
    if (gw >= N) return;
    constexpr int R = F / 32;
    float v[R];
    const float* ir = &in[(size_t)gw * F];
#pragma unroll
    for (int r = 0; r < R; r++) v[r] = ir[lane + 32 * r];
    float s = 0.f;
#pragma unroll
    for (int r = 0; r < R; r++) s += v[r];
    s = wsumf(s);
    float mean = s * (1.f / F);
    float q = 0.f;
#pragma unroll
    for (int r = 0; r < R; r++) { float d = v[r] - mean; q = fmaf(d, d, q); }
    q = wsumf(q);
    float rstd = rsqrtf(q * (1.f / F) + 1e-5f);
    float* orow = &out[(size_t)gw * F];
#pragma unroll
    for (int r = 0; r < R; r++) {
        int j = lane + 32 * r;
        float y = (v[r] - mean) * rstd * gam[j] + bet[j];
        orow[j] = eluf(y);
    }
}

// ---------------- launch ----------------
extern "C" void kernel_launch(void* const* d_in, const int* in_sizes, int n_in,
                              void* d_out, int out_size)
{
    (void)in_sizes; (void)n_in; (void)out_size;

    const float* x        = (const float*)d_in[0];
    const int*   ei       = (const int*)  d_in[1];
    const float* W_heads  = (const float*)d_in[2];
    const float* a_heads  = (const float*)d_in[3];
    const float* ev1w_h   = (const float*)d_in[4];
    const float* ev1b_h   = (const float*)d_in[5];
    const float* ev2w_h   = (const float*)d_in[6];
    const float* ev2b_h   = (const float*)d_in[7];
    const float* agg_w    = (const float*)d_in[8];
    const float* agg_b    = (const float*)d_in[9];
    const float* ln1_g    = (const float*)d_in[10];
    const float* ln1_b    = (const float*)d_in[11];
    const float* W2       = (const float*)d_in[12];
    const float* a2       = (const float*)d_in[13];
    const float* ev1w2    = (const float*)d_in[14];
    const float* ev1b2    = (const float*)d_in[15];
    const float* ev2w2    = (const float*)d_in[16];
    const float* ev2b2    = (const float*)d_in[17];
    const float* ln2_g    = (const float*)d_in[18];
    const float* ln2_b    = (const float*)d_in[19];
    const float* res_w    = (const float*)d_in[20];
    const float* res_b    = (const float*)d_in[21];

    const int* src = ei;
    const int* tgt = ei + EE;

    float* out_x  = (float*)d_out;                     // [N, 128]
    float* out_ev = (float*)d_out + (size_t)NN * DOUT; // [N, 3]

    float *Wh, *xnew, *s1, *s2, *logits, *logits2, *hbuf, *h1, *Wh2, *s1b, *s2b, *xnew2, *x2;
    cudaGetSymbolAddress((void**)&Wh,      g_Wh);
    cudaGetSymbolAddress((void**)&xnew,    g_xnew);
    cudaGetSymbolAddress((void**)&s1,      g_s1);
    cudaGetSymbolAddress((void**)&s2,      g_s2);
    cudaGetSymbolAddress((void**)&logits,  g_logits);
    cudaGetSymbolAddress((void**)&logits2, g_logits2);
    cudaGetSymbolAddress((void**)&hbuf,    g_hbuf);
    cudaGetSymbolAddress((void**)&h1,      g_h1);
    cudaGetSymbolAddress((void**)&Wh2,     g_Wh2);
    cudaGetSymbolAddress((void**)&s1b,     g_s1b);
    cudaGetSymbolAddress((void**)&s2b,     g_s2b);
    cudaGetSymbolAddress((void**)&xnew2,   g_xnew2);
    cudaGetSymbolAddress((void**)&x2,      g_x2);

    const int MB = (NN + BM - 1) / BM;   // 235

    // 0) zero accumulators + softmax scalars
    k_init<<<2048, 256>>>();

    // 1) Wh_all = x @ W_heads (head-blocked B), [30000,768]x[768,1024]
    k_sgemm<0><<<dim3((NHEAD * DH) / BN, MB), 256>>>(
        x, DIN, W_heads, DH, Wh, NHEAD * DH,
        nullptr, nullptr, 0, NN, NHEAD * DH, DIN, DH, (size_t)DIN * DH);

    // 2) per-node attention scalars, all 4 heads
    k_s1s2<<<(NN * NHEAD) / 8, 256>>>(Wh, NHEAD * DH, DH, NHEAD, a_heads, 2 * DH, s1, s2, NN);

    // 3) logits + leaky_relu + global max (slots 0..3)
    k_logits<NHEAD><<<(EE + 255) / 256, 256>>>(src, tgt, s1, s2, logits, EE, NN, 0);

    // 4) exp(l - max) in place + global sum
    k_sumexp<NHEAD><<<(EE + 255) / 256, 256>>>(logits, EE, 0);
    k_finalize<<<1, 8>>>(0, NHEAD);

    // 5) scatter-add all heads: x_new += alpha * Wh[src]
    k_scatter<NHEAD, DH><<<EE / 8, 256>>>(src, tgt, logits, Wh, NHEAD * DH, xnew, NHEAD * DH, EE, 0);

    // 6) per-head evidence: relu(x_new_h @ ev1w_h) -> softplus(@ev2w_h)+1 -> accumulate
    for (int h = 0; h < NHEAD; h++) {
        k_sgemm<1><<<dim3(1, MB), 256>>>(
            xnew + h * DH, NHEAD * DH,
            ev1w_h + (size_t)h * DH * (DH / 2), DH / 2,
            hbuf, DH / 2,
            ev1b_h + h * (DH / 2), nullptr, 0,
            NN, DH / 2, DH, DH / 2, 0);
        k_evidence<false><<<NN / 8, 256>>>(hbuf, DH / 2,
            ev2w_h + (size_t)h * (DH / 2) * NCLS, ev2b_h + h * NCLS, nullptr, NN);
    }

    // 7) h1 = elu(LN(x_cat @ agg_w + agg_b))
    k_sgemm<0><<<dim3(DH / BN, MB), 256>>>(
        xnew, NHEAD * DH, agg_w, DH, h1, DH,
        agg_b, nullptr, 0, NN, DH, NHEAD * DH, DH, 0);
    k_ln_elu<DH><<<NN / 8, 256>>>(h1, h1, ln1_g, ln1_b, NN);

    // 8) layer-2 GAT: Wh2 = h1 @ W2
    k_sgemm<0><<<dim3(1, MB), 256>>>(
        h1, DH, W2, DOUT, Wh2, DOUT,
        nullptr, nullptr, 0, NN, DOUT, DH, DOUT, 0);

    k_s1s2<<<NN / 8, 256>>>(Wh2, DOUT, DOUT, 1, a2, 2 * DOUT, s1b, s2b, NN);
    k_logits<1><<<(EE + 255) / 256, 256>>>(src, tgt, s1b, s2b, logits2, EE, NN, 4);
    k_sumexp<1><<<(EE + 255) / 256, 256>>>(logits2, EE, 4);
    k_finalize<<<1, 8>>>(4, 1);
    k_scatter<1, DOUT><<<EE / 8, 256>>>(src, tgt, logits2, Wh2, DOUT, xnew2, DOUT, EE, 4);

    // 9) evidence2 + final evidence -> d_out tail
    k_sgemm<1><<<dim3(1, MB), 256>>>(
        xnew2, DOUT, ev1w2, DOUT / 2, hbuf, DOUT / 2,
        ev1b2, nullptr, 0, NN, DOUT / 2, DOUT, DOUT / 2, 0);
    k_evidence<true><<<NN / 8, 256>>>(hbuf, DOUT / 2, ev2w2, ev2b2, out_ev, NN);

    // 10) x2 = elu(LN(x_new2)); x_out = x2 + h1 @ res_w + res_b -> d_out
    k_ln_elu<DOUT><<<NN / 8, 256>>>(xnew2, x2, ln2_g, ln2_b, NN);
    k_sgemm<2><<<dim3(1, MB), 256>>>(
        h1, DH, res_w, DOUT, out_x, DOUT,
        res_b, x2, DOUT, NN, DOUT, DH, DOUT, 0);
}

// round 6
// speedup vs baseline: 1.3217x; 1.3217x over previous
#include <cuda_runtime.h>
#include <math.h>

// ---------------- problem constants ----------------
#define NN   30000
#define EE   480000
#define DIN  768
#define DH   256    // HID
#define DOUT 128    // OUT
#define NHEAD 4
#define NCLS 3

// ---------------- scratch (static device memory; no allocations) ----------------
__device__ float    g_Wh   [(size_t)NN * (NHEAD * DH)];   // Wh all heads, [N,1024]
__device__ float    g_xnew [(size_t)NN * (NHEAD * DH)];   // x_new concat, [N,1024]
__device__ float    g_s1   [NHEAD * NN];
__device__ float    g_s2   [NHEAD * NN];
__device__ float    g_w    [(size_t)NHEAD * EE];          // unnormalized softmax weights
__device__ float    g_w2e  [EE];
__device__ float    g_hbuf [(size_t)NN * 512];            // evidence hidden (layer1: [N,512]; layer2 reuses [N,64])
__device__ float    g_evsum[NN * NCLS];
__device__ float    g_h1   [(size_t)NN * DH];
__device__ float    g_Wh2  [(size_t)NN * DOUT];
__device__ float    g_s1b  [NN];
__device__ float    g_s2b  [NN];
__device__ float    g_xnew2[(size_t)NN * DOUT];
__device__ float    g_x2   [(size_t)NN * DOUT];
__device__ unsigned g_maxenc[12];   // [0..3]=max s1 head h, [4..7]=max s2 head h, [8]=max s1b, [9]=max s2b
__device__ float    g_M    [8];     // shift per softmax slot (0..3 layer1 heads, 4 layer2)
__device__ double   g_sumexp[8];
__device__ float    g_invS  [8];

// ---------------- helpers ----------------
__device__ __forceinline__ unsigned fenc(float f) {
    unsigned u = __float_as_uint(f);
    return (u & 0x80000000u) ? ~u : (u | 0x80000000u);
}
__device__ __forceinline__ float fdec(unsigned u) {
    return (u & 0x80000000u) ? __uint_as_float(u & 0x7fffffffu) : __uint_as_float(~u);
}
__device__ __forceinline__ float wsumf(float v) {
#pragma unroll
    for (int o = 16; o > 0; o >>= 1) v += __shfl_xor_sync(0xffffffffu, v, o);
    return v;
}
__device__ __forceinline__ float softplusf(float x) {
    return fmaxf(x, 0.f) + log1pf(expf(-fabsf(x)));
}
__device__ __forceinline__ float eluf(float x) {
    return x > 0.f ? x : expm1f(x);
}
__device__ __forceinline__ void red_add_v4(float* p, float a, float b, float c, float d) {
    asm volatile("red.global.add.v4.f32 [%0], {%1, %2, %3, %4};"
                 :: "l"(p), "f"(a), "f"(b), "f"(c), "f"(d) : "memory");
}

// ---------------- init: zero accumulators + softmax scalars ----------------
__global__ void k_init() {
    size_t i = (size_t)blockIdx.x * blockDim.x + threadIdx.x;
    size_t stride = (size_t)gridDim.x * blockDim.x;
    const size_t n1 = ((size_t)NN * (NHEAD * DH)) / 4;
    float4* p1 = (float4*)g_xnew;
    float4 z = make_float4(0.f, 0.f, 0.f, 0.f);
    for (size_t j = i; j < n1; j += stride) p1[j] = z;
    const size_t n2 = ((size_t)NN * DOUT) / 4;
    float4* p2 = (float4*)g_xnew2;
    for (size_t j = i; j < n2; j += stride) p2[j] = z;
    if (i < 12) g_maxenc[i] = 0u;
    if (i < 8)  { g_sumexp[i] = 0.0; g_invS[i] = 0.f; g_M[i] = 0.f; }
}

// ---------------- generic tiled fp32 SGEMM with register prefetch ----------------
// C[M,N] = A[M, aOff + K] @ B[K,N]  (row-major).
// B head-blocked: column n lives in head n/headSize at B + head*headStrideB, local col n%headSize.
// A per-head column offset: aOff = head * aHeadStep (block-diagonal GEMMs).
// EPI: 0 = +bias; 1 = relu(+bias); 2 = +bias +addend.
#define BM 128
#define BN 128
#define BKK 16

template <int EPI>
__global__ __launch_bounds__(256, 2)
void k_sgemm(const float* __restrict__ A, int lda, int aHeadStep,
             const float* __restrict__ B, int ldb,
             float* __restrict__ C, int ldc,
             const float* __restrict__ bias,
             const float* __restrict__ addend, int ldadd,
             int M, int N, int K, int headSize, size_t headStrideB)
{
    __shared__ float As[BKK][BM + 4];
    __shared__ float Bs[BKK][BN];

    const int tid = threadIdx.x;
    const int m0 = blockIdx.y * BM;
    const int n0 = blockIdx.x * BN;

    const int head = n0 / headSize;
    const float* __restrict__ Bp = B + (size_t)head * headStrideB;
    const float* __restrict__ Ap = A + (size_t)head * aHeadStep;
    const int nloc0 = n0 - head * headSize;

    const int tm = tid >> 4;   // 0..15
    const int tn = tid & 15;   // 0..15

    // per-thread fixed smem coordinates for loads
    const int a_kk = tid & 15;          // A: column within K-tile
    const int a_m0 = tid >> 4;          // A: row base (+16*i)
    const int b_kk0 = tid >> 5;         // B: row base (+8*i)
    const int b_nb  = (tid & 31) << 2;  // B: column (float4)

    float acc[8][8];
#pragma unroll
    for (int i = 0; i < 8; i++)
#pragma unroll
        for (int j = 0; j < 8; j++) acc[i][j] = 0.f;

    float  ra[8];
    float4 rb[2];

    auto load_tiles = [&](int k0) {
#pragma unroll
        for (int i = 0; i < 8; i++) {
            int gm = m0 + a_m0 + 16 * i;
            ra[i] = (gm < M) ? Ap[(size_t)gm * lda + (k0 + a_kk)] : 0.f;
        }
#pragma unroll
        for (int i = 0; i < 2; i++) {
            int kk = b_kk0 + 8 * i;
            int gn = n0 + b_nb;
            float4 v = make_float4(0.f, 0.f, 0.f, 0.f);
            const float* bp = &Bp[(size_t)(k0 + kk) * ldb + (nloc0 + b_nb)];
            if (gn + 3 < N) {
                v = *(const float4*)bp;
            } else {
                if (gn     < N) v.x = bp[0];
                if (gn + 1 < N) v.y = bp[1];
                if (gn + 2 < N) v.z = bp[2];
            }
            rb[i] = v;
        }
    };
    auto store_tiles = [&]() {
#pragma unroll
        for (int i = 0; i < 8; i++) As[a_kk][a_m0 + 16 * i] = ra[i];
#pragma unroll
        for (int i = 0; i < 2; i++) *(float4*)&Bs[b_kk0 + 8 * i][b_nb] = rb[i];
    };
    auto compute = [&]() {
#pragma unroll
        for (int kk = 0; kk < BKK; kk++) {
            float a[8], b[8];
#pragma unroll
            for (int i = 0; i < 8; i++) a[i] = As[kk][tm * 8 + i];
#pragma unroll
            for (int j = 0; j < 8; j++) b[j] = Bs[kk][tn * 8 + j];
#pragma unroll
            for (int i = 0; i < 8; i++)
#pragma unroll
                for (int j = 0; j < 8; j++) acc[i][j] = fmaf(a[i], b[j], acc[i][j]);
        }
    };

    load_tiles(0);
    store_tiles();
    __syncthreads();
    for (int k0 = BKK; k0 < K; k0 += BKK) {
        load_tiles(k0);      // next tile -> registers (overlaps with compute)
        compute();
        __syncthreads();
        store_tiles();
        __syncthreads();
    }
    compute();

#pragma unroll
    for (int i = 0; i < 8; i++) {
        int gm = m0 + tm * 8 + i;
        if (gm < M) {
#pragma unroll
            for (int j = 0; j < 8; j++) {
                int gn = n0 + tn * 8 + j;
                if (gn < N) {
                    float v = acc[i][j];
                    if (bias) v += bias[gn];
                    if (EPI == 1) v = fmaxf(v, 0.f);
                    if (EPI == 2) v += addend[(size_t)gm * ldadd + gn];
                    C[(size_t)gm * ldc + gn] = v;
                }
            }
        }
    }
}

// ---------------- per-node attention projections + node-level max bound ----------------
// s1 = Wh.a[:F], s2 = Wh.a[F:]; atomicMax node maxima into g_maxenc[slot1+h], g_maxenc[slot2+h]
__global__ void k_s1s2(const float* __restrict__ Wh, int ld, int F, int nh,
                       const float* __restrict__ a, int aStride,
                       float* __restrict__ s1, float* __restrict__ s2, int N,
                       int slot1, int slot2)
{
    int gw = (blockIdx.x * blockDim.x + threadIdx.x) >> 5;
    int lane = threadIdx.x & 31;
    if (gw >= N * nh) return;
    int node = gw / nh;
    int h = gw - node * nh;
    const float* wr = &Wh[(size_t)node * ld + h * F];
    const float* ah = &a[(size_t)h * aStride];
    float p1 = 0.f, p2 = 0.f;
    for (int j = lane; j < F; j += 32) {
        float x = wr[j];
        p1 = fmaf(x, ah[j], p1);
        p2 = fmaf(x, ah[F + j], p2);
    }
    p1 = wsumf(p1);
    p2 = wsumf(p2);
    if (lane == 0) {
        s1[(size_t)h * N + node] = p1;
        s2[(size_t)h * N + node] = p2;
        atomicMax(&g_maxenc[slot1 + h], fenc(p1));
        atomicMax(&g_maxenc[slot2 + h], fenc(p2));
    }
}

// M[slot+h] = leaky_relu(max_s1 + max_s2)  — an upper bound on the true edge max;
// any finite shift leaves softmax exactly invariant.
__global__ void k_prepM(int slot, int slot1, int slot2, int n)
{
    int i = threadIdx.x;
    if (i < n) {
        float l = fdec(g_maxenc[slot1 + i]) + fdec(g_maxenc[slot2 + i]);
        g_M[slot + i] = (l > 0.f) ? l : 0.2f * l;
    }
}

// ---------------- single edge pass: w = exp(lrelu(s1[src]+s2[tgt]) - M), block-sum ----------------
template <int NH>
__global__ void k_expsum(const int* __restrict__ src, const int* __restrict__ tgt,
                         const float* __restrict__ s1, const float* __restrict__ s2,
                         float* __restrict__ w, int E, int N, int slot)
{
    int e = blockIdx.x * blockDim.x + threadIdx.x;
    bool ok = (e < E);
    int s = 0, t = 0;
    if (ok) { s = src[e]; t = tgt[e]; }
    float sv[NH];
#pragma unroll
    for (int h = 0; h < NH; h++) {
        float v = 0.f;
        if (ok) {
            float l = s1[(size_t)h * N + s] + s2[(size_t)h * N + t];
            l = (l > 0.f) ? l : 0.2f * l;
            v = expf(l - g_M[slot + h]);
            w[(size_t)h * E + e] = v;
        }
        sv[h] = v;
    }
    __shared__ float red[256];
#pragma unroll
    for (int h = 0; h < NH; h++) {
        red[threadIdx.x] = sv[h];
        __syncthreads();
        for (int sft = 128; sft > 0; sft >>= 1) {
            if (threadIdx.x < sft) red[threadIdx.x] += red[threadIdx.x + sft];
            __syncthreads();
        }
        if (threadIdx.x == 0) atomicAdd(&g_sumexp[slot + h], (double)red[0]);
        __syncthreads();
    }
}

__global__ void k_finalize(int slot0, int n)
{
    int i = threadIdx.x;
    if (i < n) g_invS[slot0 + i] = (float)(1.0 / g_sumexp[slot0 + i]);
}

// ---------------- scatter: x_new[tgt] += alpha * Wh[src]  (warp/edge, v4 reductions) ----------------
template <int NH, int F>
__global__ void k_scatter(const int* __restrict__ src, const int* __restrict__ tgt,
                          const float* __restrict__ w,
                          const float* __restrict__ Wh, int ldWh,
                          float* __restrict__ xnew, int ldx, int E, int slot0)
{
    int gw = (blockIdx.x * blockDim.x + threadIdx.x) >> 5;
    int lane = threadIdx.x & 31;
    if (gw >= E) return;
    int s = src[gw], t = tgt[gw];
#pragma unroll
    for (int h = 0; h < NH; h++) {
        float c = w[(size_t)h * E + gw] * g_invS[slot0 + h];
        const float* wrow = &Wh[(size_t)s * ldWh + h * F];
        float*       xrow = &xnew[(size_t)t * ldx + h * F];
#pragma unroll
        for (int j0 = 0; j0 < F; j0 += 128) {
            int j = j0 + lane * 4;
            float4 v = *(const float4*)&wrow[j];
            red_add_v4(&xrow[j], c * v.x, c * v.y, c * v.z, c * v.w);
        }
    }
}

// ---------------- evidence layer 1 (all 4 heads): evsum[n,c] = sum_h softplus(h_n @ w2_h + b2_h)+1 ----------------
__global__ void k_evid1(const float* __restrict__ hbuf,   // [N,512] (4 heads x 128)
                        const float* __restrict__ w2,     // [4][128,3]
                        const float* __restrict__ b2,     // [4][3]
                        float* __restrict__ evsum, int N)
{
    int gw = (blockIdx.x * blockDim.x + threadIdx.x) >> 5;
    int lane = threadIdx.x & 31;
    if (gw >= N) return;
    float e0 = 0.f, e1 = 0.f, e2 = 0.f;
#pragma unroll
    for (int h = 0; h < NHEAD; h++) {
        float4 v = *(const float4*)&hbuf[(size_t)gw * 512 + h * 128 + lane * 4];
        const float* wc = &w2[h * 384 + lane * 12];
        float a0 = v.x * wc[0] + v.y * wc[3] + v.z * wc[6] + v.w * wc[9];
        float a1 = v.x * wc[1] + v.y * wc[4] + v.z * wc[7] + v.w * wc[10];
        float a2 = v.x * wc[2] + v.y * wc[5] + v.z * wc[8] + v.w * wc[11];
        a0 = wsumf(a0); a1 = wsumf(a1); a2 = wsumf(a2);
        e0 += softplusf(a0 + b2[h * 3 + 0]) + 1.f;
        e1 += softplusf(a1 + b2[h * 3 + 1]) + 1.f;
        e2 += softplusf(a2 + b2[h * 3 + 2]) + 1.f;
    }
    if (lane == 0) {
        evsum[gw * 3 + 0] = e0;
        evsum[gw * 3 + 1] = e1;
        evsum[gw * 3 + 2] = e2;
    }
}

// ---------------- evidence layer 2 + final combine -> out ----------------
__global__ void k_evid2(const float* __restrict__ hbuf,   // [N,64]
                        const float* __restrict__ w2,     // [64,3]
                        const float* __restrict__ b2,     // [3]
                        const float* __restrict__ evsum,
                        float* __restrict__ out, int N)
{
    int gw = (blockIdx.x * blockDim.x + threadIdx.x) >> 5;
    int lane = threadIdx.x & 31;
    if (gw >= N) return;
    float2 v = *(const float2*)&hbuf[(size_t)gw * 64 + lane * 2];
    const float* wc = &w2[lane * 6];
    float a0 = v.x * wc[0] + v.y * wc[3];
    float a1 = v.x * wc[1] + v.y * wc[4];
    float a2 = v.x * wc[2] + v.y * wc[5];
    a0 = wsumf(a0); a1 = wsumf(a1); a2 = wsumf(a2);
    if (lane == 0) {
        float e0 = softplusf(a0 + b2[0]) + 1.f;
        float e1 = softplusf(a1 + b2[1]) + 1.f;
        float e2 = softplusf(a2 + b2[2]) + 1.f;
        out[(size_t)gw * 3 + 0] = (evsum[gw * 3 + 0] * 0.25f + e0) * 0.5f;
        out[(size_t)gw * 3 + 1] = (evsum[gw * 3 + 1] * 0.25f + e1) * 0.5f;
        out[(size_t)gw * 3 + 2] = (evsum[gw * 3 + 2] * 0.25f + e2) * 0.5f;
    }
}

// ---------------- LayerNorm (population var, eps=1e-5) + ELU, warp per row ----------------
template <int F>
__global__ void k_ln_elu(const float* __restrict__ in, float* __restrict__ out,
                         const float* __restrict__ gam, const float* __restrict__ bet, int N)
{
    int gw = (blockIdx.x * blockDim.x + threadIdx.x) >> 5;
    int lane = threadIdx.x & 31;
    if (gw >= N) return;
    constexpr int R = F / 32;
    float v[R];
    const float* ir = &in[(size_t)gw * F];
#pragma unroll
    for (int r = 0; r < R; r++) v[r] = ir[lane + 32 * r];
    float s = 0.f;
#pragma unroll
    for (int r = 0; r < R; r++) s += v[r];
    s = wsumf(s);
    float mean = s * (1.f / F);
    float q = 0.f;
#pragma unroll
    for (int r = 0; r < R; r++) { float d = v[r] - mean; q = fmaf(d, d, q); }
    q = wsumf(q);
    float rstd = rsqrtf(q * (1.f / F) + 1e-5f);
    float* orow = &out[(size_t)gw * F];
#pragma unroll
    for (int r = 0; r < R; r++) {
        int j = lane + 32 * r;
        float y = (v[r] - mean) * rstd * gam[j] + bet[j];
        orow[j] = eluf(y);
    }
}

// ---------------- launch ----------------
extern "C" void kernel_launch(void* const* d_in, const int* in_sizes, int n_in,
                              void* d_out, int out_size)
{
    (void)in_sizes; (void)n_in; (void)out_size;

    const float* x        = (const float*)d_in[0];
    const int*   ei       = (const int*)  d_in[1];
    const float* W_heads  = (const float*)d_in[2];
    const float* a_heads  = (const float*)d_in[3];
    const float* ev1w_h   = (const float*)d_in[4];
    const float* ev1b_h   = (const float*)d_in[5];
    const float* ev2w_h   = (const float*)d_in[6];
    const float* ev2b_h   = (const float*)d_in[7];
    const float* agg_w    = (const float*)d_in[8];
    const float* agg_b    = (const float*)d_in[9];
    const float* ln1_g    = (const float*)d_in[10];
    const float* ln1_b    = (const float*)d_in[11];
    const float* W2       = (const float*)d_in[12];
    const float* a2       = (const float*)d_in[13];
    const float* ev1w2    = (const float*)d_in[14];
    const float* ev1b2    = (const float*)d_in[15];
    const float* ev2w2    = (const float*)d_in[16];
    const float* ev2b2    = (const float*)d_in[17];
    const float* ln2_g    = (const float*)d_in[18];
    const float* ln2_b    = (const float*)d_in[19];
    const float* res_w    = (const float*)d_in[20];
    const float* res_b    = (const float*)d_in[21];

    const int* src = ei;
    const int* tgt = ei + EE;

    float* out_x  = (float*)d_out;                     // [N, 128]
    float* out_ev = (float*)d_out + (size_t)NN * DOUT; // [N, 3]

    float *Wh, *xnew, *s1, *s2, *wbuf, *w2e, *hbuf, *evsum, *h1, *Wh2, *s1b, *s2b, *xnew2, *x2;
    cudaGetSymbolAddress((void**)&Wh,    g_Wh);
    cudaGetSymbolAddress((void**)&xnew,  g_xnew);
    cudaGetSymbolAddress((void**)&s1,    g_s1);
    cudaGetSymbolAddress((void**)&s2,    g_s2);
    cudaGetSymbolAddress((void**)&wbuf,  g_w);
    cudaGetSymbolAddress((void**)&w2e,   g_w2e);
    cudaGetSymbolAddress((void**)&hbuf,  g_hbuf);
    cudaGetSymbolAddress((void**)&evsum, g_evsum);
    cudaGetSymbolAddress((void**)&h1,    g_h1);
    cudaGetSymbolAddress((void**)&Wh2,   g_Wh2);
    cudaGetSymbolAddress((void**)&s1b,   g_s1b);
    cudaGetSymbolAddress((void**)&s2b,   g_s2b);
    cudaGetSymbolAddress((void**)&xnew2, g_xnew2);
    cudaGetSymbolAddress((void**)&x2,    g_x2);

    const int MB = (NN + BM - 1) / BM;   // 235

    // 0) zero accumulators + softmax scalars
    k_init<<<2048, 256>>>();

    // 1) Wh_all = x @ W_heads (head-blocked B), [30000,768]x[768,1024]
    k_sgemm<0><<<dim3((NHEAD * DH) / BN, MB), 256>>>(
        x, DIN, 0, W_heads, DH, Wh, NHEAD * DH,
        nullptr, nullptr, 0, NN, NHEAD * DH, DIN, DH, (size_t)DIN * DH);

    // 2) per-node attention scalars + node maxima (all 4 heads)
    k_s1s2<<<(NN * NHEAD) / 8, 256>>>(Wh, NHEAD * DH, DH, NHEAD, a_heads, 2 * DH, s1, s2, NN, 0, 4);
    k_prepM<<<1, 8>>>(0, 0, 4, NHEAD);

    // 3) single edge pass: w = exp(lrelu(s1+s2)-M), global sum
    k_expsum<NHEAD><<<(EE + 255) / 256, 256>>>(src, tgt, s1, s2, wbuf, EE, NN, 0);
    k_finalize<<<1, 8>>>(0, NHEAD);

    // 4) scatter-add all heads: x_new += (w*invS) * Wh[src]
    k_scatter<NHEAD, DH><<<EE / 8, 256>>>(src, tgt, wbuf, Wh, NHEAD * DH, xnew, NHEAD * DH, EE, 0);

    // 5) evidence layer 1: one block-diagonal GEMM (4 heads) + fused head
    k_sgemm<1><<<dim3(4, MB), 256>>>(
        xnew, NHEAD * DH, DH,
        ev1w_h, DH / 2,
        hbuf, 512,
        ev1b_h, nullptr, 0,
        NN, 512, DH, DH / 2, (size_t)DH * (DH / 2));
    k_evid1<<<NN / 8, 256>>>(hbuf, ev2w_h, ev2b_h, evsum, NN);

    // 6) h1 = elu(LN(x_cat @ agg_w + agg_b))
    k_sgemm<0><<<dim3(DH / BN, MB), 256>>>(
        xnew, NHEAD * DH, 0, agg_w, DH, h1, DH,
        agg_b, nullptr, 0, NN, DH, NHEAD * DH, DH, 0);
    k_ln_elu<DH><<<NN / 8, 256>>>(h1, h1, ln1_g, ln1_b, NN);

    // 7) layer-2 GAT
    k_sgemm<0><<<dim3(1, MB), 256>>>(
        h1, DH, 0, W2, DOUT, Wh2, DOUT,
        nullptr, nullptr, 0, NN, DOUT, DH, DOUT, 0);

    k_s1s2<<<NN / 8, 256>>>(Wh2, DOUT, DOUT, 1, a2, 2 * DOUT, s1b, s2b, NN, 8, 9);
    k_prepM<<<1, 8>>>(4, 8, 9, 1);
    k_expsum<1><<<(EE + 255) / 256, 256>>>(src, tgt, s1b, s2b, w2e, EE, NN, 4);
    k_finalize<<<1, 8>>>(4, 1);
    k_scatter<1, DOUT><<<EE / 8, 256>>>(src, tgt, w2e, Wh2, DOUT, xnew2, DOUT, EE, 4);

    // 8) evidence layer 2 + final combine -> d_out tail
    k_sgemm<1><<<dim3(1, MB), 256>>>(
        xnew2, DOUT, 0, ev1w2, DOUT / 2, hbuf, DOUT / 2,
        ev1b2, nullptr, 0, NN, DOUT / 2, DOUT, DOUT / 2, 0);
    k_evid2<<<NN / 8, 256>>>(hbuf, ev2w2, ev2b2, evsum, out_ev, NN);

    // 9) x2 = elu(LN(x_new2)); x_out = x2 + h1 @ res_w + res_b -> d_out
    k_ln_elu<DOUT><<<NN / 8, 256>>>(xnew2, x2, ln2_g, ln2_b, NN);
    k_sgemm<2><<<dim3(1, MB), 256>>>(
        h1, DH, 0, res_w, DOUT, out_x, DOUT,
        res_b, x2, DOUT, NN, DOUT, DH, DOUT, 0);
}

// round 8
// speedup vs baseline: 2.1659x; 1.6387x over previous
#include <cuda_runtime.h>
#include <cuda_bf16.h>
#include <math.h>
#include <stdint.h>

// ---------------- problem constants ----------------
#define NN   30000
#define EE   480000
#define DIN  768
#define DH   256    // HID
#define DOUT 128    // OUT
#define NHEAD 4
#define NCLS 3

// ---------------- scratch (static device memory; no allocations) ----------------
__device__ float    g_Wh   [(size_t)NN * (NHEAD * DH)];
__device__ float    g_xnew [(size_t)NN * (NHEAD * DH)];
__device__ float    g_s1   [NHEAD * NN];
__device__ float    g_s2   [NHEAD * NN];
__device__ float    g_w    [(size_t)NHEAD * EE];
__device__ float    g_w2e  [EE];
__device__ float    g_hbuf [(size_t)NN * 512];
__device__ float    g_evsum[NN * NCLS];
__device__ float    g_h1   [(size_t)NN * DH];
__device__ float    g_Wh2  [(size_t)NN * DOUT];
__device__ float    g_s1b  [NN];
__device__ float    g_s2b  [NN];
__device__ float    g_xnew2[(size_t)NN * DOUT];
__device__ float    g_x2   [(size_t)NN * DOUT];
__device__ unsigned g_maxenc[12];
__device__ float    g_M    [8];
__device__ double   g_sumexp[8];
__device__ float    g_invS  [8];

// transposed + bf16-split weights (Bt[n][k], K-major)
__device__ __nv_bfloat16 g_bt1hi [1024 * 768], g_bt1lo [1024 * 768];   // W_heads
__device__ __nv_bfloat16 g_btahi [256 * 1024], g_btalo [256 * 1024];   // agg_w
__device__ __nv_bfloat16 g_btehi [512 * 256],  g_btelo [512 * 256];    // ev1w_heads
__device__ __nv_bfloat16 g_btw2hi[128 * 256],  g_btw2lo[128 * 256];    // W2
__device__ __nv_bfloat16 g_btrhi [128 * 256],  g_btrlo [128 * 256];    // res_w

// ---------------- helpers ----------------
__device__ __forceinline__ unsigned fenc(float f) {
    unsigned u = __float_as_uint(f);
    return (u & 0x80000000u) ? ~u : (u | 0x80000000u);
}
__device__ __forceinline__ float fdec(unsigned u) {
    return (u & 0x80000000u) ? __uint_as_float(u & 0x7fffffffu) : __uint_as_float(~u);
}
__device__ __forceinline__ float wsumf(float v) {
#pragma unroll
    for (int o = 16; o > 0; o >>= 1) v += __shfl_xor_sync(0xffffffffu, v, o);
    return v;
}
__device__ __forceinline__ float softplusf(float x) {
    return fmaxf(x, 0.f) + log1pf(expf(-fabsf(x)));
}
__device__ __forceinline__ float eluf(float x) {
    return x > 0.f ? x : expm1f(x);
}
__device__ __forceinline__ void red_add_v4(float* p, float a, float b, float c, float d) {
    asm volatile("red.global.add.v4.f32 [%0], {%1, %2, %3, %4};"
                 :: "l"(p), "f"(a), "f"(b), "f"(c), "f"(d) : "memory");
}
__device__ __forceinline__ void bf16split(float x, __nv_bfloat16& hi, __nv_bfloat16& lo) {
    hi = __float2bfloat16(x);
    lo = __float2bfloat16(x - __bfloat162float(hi));
}

// mma.sync m16n8k16 bf16 (row.col), fp32 accumulate — no arch-feature gate, runs on sm_103.
__device__ __forceinline__ void mma_bf16(float* c, const uint32_t* a, const uint32_t* b) {
    asm volatile(
        "mma.sync.aligned.m16n8k16.row.col.f32.bf16.bf16.f32 "
        "{%0,%1,%2,%3}, {%4,%5,%6,%7}, {%8,%9}, {%0,%1,%2,%3};"
        : "+f"(c[0]), "+f"(c[1]), "+f"(c[2]), "+f"(c[3])
        : "r"(a[0]), "r"(a[1]), "r"(a[2]), "r"(a[3]), "r"(b[0]), "r"(b[1]));
}

// ---------------- init ----------------
__global__ void k_init() {
    size_t i = (size_t)blockIdx.x * blockDim.x + threadIdx.x;
    size_t stride = (size_t)gridDim.x * blockDim.x;
    const size_t n1 = ((size_t)NN * (NHEAD * DH)) / 4;
    float4* p1 = (float4*)g_xnew;
    float4 z = make_float4(0.f, 0.f, 0.f, 0.f);
    for (size_t j = i; j < n1; j += stride) p1[j] = z;
    const size_t n2 = ((size_t)NN * DOUT) / 4;
    float4* p2 = (float4*)g_xnew2;
    for (size_t j = i; j < n2; j += stride) p2[j] = z;
    if (i < 12) g_maxenc[i] = 0u;
    if (i < 8)  { g_sumexp[i] = 0.0; g_invS[i] = 0.f; g_M[i] = 0.f; }
}

// ---------------- B transpose + bf16 split (one-time, tiny) ----------------
__global__ void k_bt(const float* __restrict__ src, __nv_bfloat16* __restrict__ bthi,
                     __nv_bfloat16* __restrict__ btlo, int K, int nTotal, int headN, int headStride)
{
    int idx = blockIdx.x * blockDim.x + threadIdx.x;
    if (idx >= nTotal * K) return;
    int n = idx / K, k = idx - n * K;
    int head = n / headN, nloc = n - head * headN;
    float v = src[(size_t)head * headStride + (size_t)k * headN + nloc];
    __nv_bfloat16 hi, lo;
    bf16split(v, hi, lo);
    bthi[idx] = hi;
    btlo[idx] = lo;
}

// ---------------- bf16-split tensor-core GEMM: C[M, 128*gx] = A @ Bt^T ----------------
// A fp32 [M,lda] (split in load path); Bt pre-split bf16 [Ntot,K] K-major.
// Per-head A column offset: aOff = (n0/headN)*aHeadStep.
// EPI: 0 = (+bias); 1 = relu(+bias); 2 = +bias +addend.
#define ASTR 40   // smem row stride in bf16 elems (80B, 16B-aligned, conflict-free frags)

template <int EPI>
__global__ __launch_bounds__(256, 1)
void k_mma(const float* __restrict__ A, int lda, int aHeadStep, int headN,
           const __nv_bfloat16* __restrict__ Bthi, const __nv_bfloat16* __restrict__ Btlo,
           float* __restrict__ C, int ldc,
           const float* __restrict__ bias,
           const float* __restrict__ addend, int ldadd,
           int M, int K)
{
    __shared__ __nv_bfloat16 sAhi[128 * ASTR];
    __shared__ __nv_bfloat16 sAlo[128 * ASTR];
    __shared__ __nv_bfloat16 sBhi[128 * ASTR];
    __shared__ __nv_bfloat16 sBlo[128 * ASTR];

    const int tid = threadIdx.x;
    const int lane = tid & 31;
    const int wid = tid >> 5;
    const int warp_m = wid & 1;        // 2 warps in M
    const int warp_n = wid >> 1;       // 4 warps in N
    const int g  = lane >> 2;          // group 0..7
    const int tg = lane & 3;           // thread-in-group

    const int m0 = blockIdx.y * 128;
    const int n0 = blockIdx.x * 128;
    const float* __restrict__ Ap = A + (size_t)(n0 / headN) * aHeadStep;

    float acc[4][4][4];
#pragma unroll
    for (int i = 0; i < 4; i++)
#pragma unroll
        for (int j = 0; j < 4; j++)
#pragma unroll
            for (int k = 0; k < 4; k++) acc[i][j][k] = 0.f;

    // register staging for next tile
    float4 ra[4];
    uint4  rbh[2], rbl[2];

    auto load_tiles = [&](int k0) {
#pragma unroll
        for (int i = 0; i < 4; i++) {
            int idx = tid + 256 * i;
            int row = idx >> 3, c4 = (idx & 7) << 2;
            int gm = m0 + row;
            ra[i] = (gm < M) ? *(const float4*)&Ap[(size_t)gm * lda + k0 + c4]
                             : make_float4(0.f, 0.f, 0.f, 0.f);
        }
#pragma unroll
        for (int i = 0; i < 2; i++) {
            int idx = tid + 256 * i;
            int row = idx >> 2, c8 = (idx & 3) << 3;
            size_t gi = (size_t)(n0 + row) * K + k0 + c8;
            rbh[i] = *(const uint4*)&Bthi[gi];
            rbl[i] = *(const uint4*)&Btlo[gi];
        }
    };
    auto store_tiles = [&]() {
#pragma unroll
        for (int i = 0; i < 4; i++) {
            int idx = tid + 256 * i;
            int row = idx >> 3, c4 = (idx & 7) << 2;
            __nv_bfloat16 hx, lx, hy, ly, hz, lz, hw, lw;
            bf16split(ra[i].x, hx, lx); bf16split(ra[i].y, hy, ly);
            bf16split(ra[i].z, hz, lz); bf16split(ra[i].w, hw, lw);
            int o = row * ASTR + c4;
            *(__nv_bfloat162*)&sAhi[o]     = __nv_bfloat162(hx, hy);
            *(__nv_bfloat162*)&sAhi[o + 2] = __nv_bfloat162(hz, hw);
            *(__nv_bfloat162*)&sAlo[o]     = __nv_bfloat162(lx, ly);
            *(__nv_bfloat162*)&sAlo[o + 2] = __nv_bfloat162(lz, lw);
        }
#pragma unroll
        for (int i = 0; i < 2; i++) {
            int idx = tid + 256 * i;
            int row = idx >> 2, c8 = (idx & 3) << 3;
            *(uint4*)&sBhi[row * ASTR + c8] = rbh[i];
            *(uint4*)&sBlo[row * ASTR + c8] = rbl[i];
        }
    };
    auto compute = [&]() {
#pragma unroll
        for (int kc = 0; kc < 32; kc += 16) {
            uint32_t ah[4][4], al[4][4];
#pragma unroll
            for (int mt = 0; mt < 4; mt++) {
                int base = (warp_m * 64 + mt * 16 + g) * ASTR + kc + tg * 2;
                ah[mt][0] = *(const uint32_t*)&sAhi[base];
                ah[mt][1] = *(const uint32_t*)&sAhi[base + 8 * ASTR];
                ah[mt][2] = *(const uint32_t*)&sAhi[base + 8];
                ah[mt][3] = *(const uint32_t*)&sAhi[base + 8 * ASTR + 8];
                al[mt][0] = *(const uint32_t*)&sAlo[base];
                al[mt][1] = *(const uint32_t*)&sAlo[base + 8 * ASTR];
                al[mt][2] = *(const uint32_t*)&sAlo[base + 8];
                al[mt][3] = *(const uint32_t*)&sAlo[base + 8 * ASTR + 8];
            }
            uint32_t bh[4][2], bl[4][2];
#pragma unroll
            for (int nt = 0; nt < 4; nt++) {
                int base = (warp_n * 32 + nt * 8 + g) * ASTR + kc + tg * 2;
                bh[nt][0] = *(const uint32_t*)&sBhi[base];
                bh[nt][1] = *(const uint32_t*)&sBhi[base + 8];
                bl[nt][0] = *(const uint32_t*)&sBlo[base];
                bl[nt][1] = *(const uint32_t*)&sBlo[base + 8];
            }
#pragma unroll
            for (int mt = 0; mt < 4; mt++)
#pragma unroll
                for (int nt = 0; nt < 4; nt++) {
                    mma_bf16(acc[mt][nt], ah[mt], bh[nt]);
                    mma_bf16(acc[mt][nt], ah[mt], bl[nt]);
                    mma_bf16(acc[mt][nt], al[mt], bh[nt]);
                }
        }
    };

    load_tiles(0);
    store_tiles();
    __syncthreads();
    for (int k0 = 32; k0 < K; k0 += 32) {
        load_tiles(k0);          // next tile in flight during compute
        compute();
        __syncthreads();
        store_tiles();
        __syncthreads();
    }
    compute();

    // epilogue
#pragma unroll
    for (int mt = 0; mt < 4; mt++) {
        int r0 = m0 + warp_m * 64 + mt * 16 + g;
#pragma unroll
        for (int nt = 0; nt < 4; nt++) {
            int gc = n0 + warp_n * 32 + nt * 8 + tg * 2;
            float2 v01 = make_float2(acc[mt][nt][0], acc[mt][nt][1]);
            float2 v23 = make_float2(acc[mt][nt][2], acc[mt][nt][3]);
            if (bias) {
                float2 b = *(const float2*)&bias[gc];
                v01.x += b.x; v01.y += b.y;
                v23.x += b.x; v23.y += b.y;
            }
            if (EPI == 1) {
                v01.x = fmaxf(v01.x, 0.f); v01.y = fmaxf(v01.y, 0.f);
                v23.x = fmaxf(v23.x, 0.f); v23.y = fmaxf(v23.y, 0.f);
            }
            if (r0 < M) {
                if (EPI == 2) {
                    float2 adx = *(const float2*)&addend[(size_t)r0 * ldadd + gc];
                    v01.x += adx.x; v01.y += adx.y;
                }
                *(float2*)&C[(size_t)r0 * ldc + gc] = v01;
            }
            if (r0 + 8 < M) {
                if (EPI == 2) {
                    float2 adx = *(const float2*)&addend[(size_t)(r0 + 8) * ldadd + gc];
                    v23.x += adx.x; v23.y += adx.y;
                }
                *(float2*)&C[(size_t)(r0 + 8) * ldc + gc] = v23;
            }
        }
    }
}

// ---------------- fp32 SGEMM (small evidence-2 GEMM only) ----------------
#define BM 128
#define BN 128
#define BKK 16
template <int EPI>
__global__ __launch_bounds__(256, 2)
void k_sgemm(const float* __restrict__ A, int lda,
             const float* __restrict__ B, int ldb,
             float* __restrict__ C, int ldc,
             const float* __restrict__ bias,
             int M, int N, int K)
{
    __shared__ float As[BKK][BM + 4];
    __shared__ float Bs[BKK][BN];
    const int tid = threadIdx.x;
    const int m0 = blockIdx.y * BM;
    const int n0 = blockIdx.x * BN;
    const int tm = tid >> 4, tn = tid & 15;
    const int a_kk = tid & 15, a_m0 = tid >> 4;
    const int b_kk0 = tid >> 5, b_nb = (tid & 31) << 2;

    float acc[8][8];
#pragma unroll
    for (int i = 0; i < 8; i++)
#pragma unroll
        for (int j = 0; j < 8; j++) acc[i][j] = 0.f;

    float ra[8]; float4 rb[2];
    auto load_tiles = [&](int k0) {
#pragma unroll
        for (int i = 0; i < 8; i++) {
            int gm = m0 + a_m0 + 16 * i;
            ra[i] = (gm < M) ? A[(size_t)gm * lda + (k0 + a_kk)] : 0.f;
        }
#pragma unroll
        for (int i = 0; i < 2; i++) {
            int kk = b_kk0 + 8 * i;
            int gn = n0 + b_nb;
            float4 v = make_float4(0.f, 0.f, 0.f, 0.f);
            const float* bp = &B[(size_t)(k0 + kk) * ldb + b_nb];
            if (gn + 3 < N) v = *(const float4*)bp;
            else {
                if (gn     < N) v.x = bp[0];
                if (gn + 1 < N) v.y = bp[1];
                if (gn + 2 < N) v.z = bp[2];
            }
            rb[i] = v;
        }
    };
    auto store_tiles = [&]() {
#pragma unroll
        for (int i = 0; i < 8; i++) As[a_kk][a_m0 + 16 * i] = ra[i];
#pragma unroll
        for (int i = 0; i < 2; i++) *(float4*)&Bs[b_kk0 + 8 * i][b_nb] = rb[i];
    };
    auto compute = [&]() {
#pragma unroll
        for (int kk = 0; kk < BKK; kk++) {
            float a[8], b[8];
#pragma unroll
            for (int i = 0; i < 8; i++) a[i] = As[kk][tm * 8 + i];
#pragma unroll
            for (int j = 0; j < 8; j++) b[j] = Bs[kk][tn * 8 + j];
#pragma unroll
            for (int i = 0; i < 8; i++)
#pragma unroll
                for (int j = 0; j < 8; j++) acc[i][j] = fmaf(a[i], b[j], acc[i][j]);
        }
    };
    load_tiles(0); store_tiles(); __syncthreads();
    for (int k0 = BKK; k0 < K; k0 += BKK) {
        load_tiles(k0); compute(); __syncthreads(); store_tiles(); __syncthreads();
    }
    compute();
#pragma unroll
    for (int i = 0; i < 8; i++) {
        int gm = m0 + tm * 8 + i;
        if (gm < M) {
#pragma unroll
            for (int j = 0; j < 8; j++) {
                int gn = n0 + tn * 8 + j;
                if (gn < N) {
                    float v = acc[i][j];
                    if (bias) v += bias[gn];
                    if (EPI == 1) v = fmaxf(v, 0.f);
                    C[(size_t)gm * ldc + gn] = v;
                }
            }
        }
    }
}

// ---------------- attention projections + node maxima ----------------
__global__ void k_s1s2(const float* __restrict__ Wh, int ld, int F, int nh,
                       const float* __restrict__ a, int aStride,
                       float* __restrict__ s1, float* __restrict__ s2, int N,
                       int slot1, int slot2)
{
    int gw = (blockIdx.x * blockDim.x + threadIdx.x) >> 5;
    int lane = threadIdx.x & 31;
    if (gw >= N * nh) return;
    int node = gw / nh;
    int h = gw - node * nh;
    const float* wr = &Wh[(size_t)node * ld + h * F];
    const float* ah = &a[(size_t)h * aStride];
    float p1 = 0.f, p2 = 0.f;
    for (int j = lane; j < F; j += 32) {
        float x = wr[j];
        p1 = fmaf(x, ah[j], p1);
        p2 = fmaf(x, ah[F + j], p2);
    }
    p1 = wsumf(p1); p2 = wsumf(p2);
    if (lane == 0) {
        s1[(size_t)h * N + node] = p1;
        s2[(size_t)h * N + node] = p2;
        atomicMax(&g_maxenc[slot1 + h], fenc(p1));
        atomicMax(&g_maxenc[slot2 + h], fenc(p2));
    }
}

__global__ void k_prepM(int slot, int slot1, int slot2, int n)
{
    int i = threadIdx.x;
    if (i < n) {
        float l = fdec(g_maxenc[slot1 + i]) + fdec(g_maxenc[slot2 + i]);
        g_M[slot + i] = (l > 0.f) ? l : 0.2f * l;
    }
}

template <int NH>
__global__ void k_expsum(const int* __restrict__ src, const int* __restrict__ tgt,
                         const float* __restrict__ s1, const float* __restrict__ s2,
                         float* __restrict__ w, int E, int N, int slot)
{
    int e = blockIdx.x * blockDim.x + threadIdx.x;
    bool ok = (e < E);
    int s = 0, t = 0;
    if (ok) { s = src[e]; t = tgt[e]; }
    float sv[NH];
#pragma unroll
    for (int h = 0; h < NH; h++) {
        float v = 0.f;
        if (ok) {
            float l = s1[(size_t)h * N + s] + s2[(size_t)h * N + t];
            l = (l > 0.f) ? l : 0.2f * l;
            v = expf(l - g_M[slot + h]);
            w[(size_t)h * E + e] = v;
        }
        sv[h] = v;
    }
    __shared__ float red[256];
#pragma unroll
    for (int h = 0; h < NH; h++) {
        red[threadIdx.x] = sv[h];
        __syncthreads();
        for (int sft = 128; sft > 0; sft >>= 1) {
            if (threadIdx.x < sft) red[threadIdx.x] += red[threadIdx.x + sft];
            __syncthreads();
        }
        if (threadIdx.x == 0) atomicAdd(&g_sumexp[slot + h], (double)red[0]);
        __syncthreads();
    }
}

__global__ void k_finalize(int slot0, int n)
{
    int i = threadIdx.x;
    if (i < n) g_invS[slot0 + i] = (float)(1.0 / g_sumexp[slot0 + i]);
}

// ---------------- scatter ----------------
template <int NH, int F>
__global__ void k_scatter(const int* __restrict__ src, const int* __restrict__ tgt,
                          const float* __restrict__ w,
                          const float* __restrict__ Wh, int ldWh,
                          float* __restrict__ xnew, int ldx, int E, int slot0)
{
    int gw = (blockIdx.x * blockDim.x + threadIdx.x) >> 5;
    int lane = threadIdx.x & 31;
    if (gw >= E) return;
    int s = src[gw], t = tgt[gw];
#pragma unroll
    for (int h = 0; h < NH; h++) {
        float c = w[(size_t)h * E + gw] * g_invS[slot0 + h];
        const float* wrow = &Wh[(size_t)s * ldWh + h * F];
        float*       xrow = &xnew[(size_t)t * ldx + h * F];
#pragma unroll
        for (int j0 = 0; j0 < F; j0 += 128) {
            int j = j0 + lane * 4;
            float4 v = *(const float4*)&wrow[j];
            red_add_v4(&xrow[j], c * v.x, c * v.y, c * v.z, c * v.w);
        }
    }
}

// ---------------- evidence heads ----------------
__global__ void k_evid1(const float* __restrict__ hbuf, const float* __restrict__ w2,
                        const float* __restrict__ b2, float* __restrict__ evsum, int N)
{
    int gw = (blockIdx.x * blockDim.x + threadIdx.x) >> 5;
    int lane = threadIdx.x & 31;
    if (gw >= N) return;
    float e0 = 0.f, e1 = 0.f, e2 = 0.f;
#pragma unroll
    for (int h = 0; h < NHEAD; h++) {
        float4 v = *(const float4*)&hbuf[(size_t)gw * 512 + h * 128 + lane * 4];
        const float* wc = &w2[h * 384 + lane * 12];
        float a0 = v.x * wc[0] + v.y * wc[3] + v.z * wc[6] + v.w * wc[9];
        float a1 = v.x * wc[1] + v.y * wc[4] + v.z * wc[7] + v.w * wc[10];
        float a2 = v.x * wc[2] + v.y * wc[5] + v.z * wc[8] + v.w * wc[11];
        a0 = wsumf(a0); a1 = wsumf(a1); a2 = wsumf(a2);
        e0 += softplusf(a0 + b2[h * 3 + 0]) + 1.f;
        e1 += softplusf(a1 + b2[h * 3 + 1]) + 1.f;
        e2 += softplusf(a2 + b2[h * 3 + 2]) + 1.f;
    }
    if (lane == 0) {
        evsum[gw * 3 + 0] = e0; evsum[gw * 3 + 1] = e1; evsum[gw * 3 + 2] = e2;
    }
}

__global__ void k_evid2(const float* __restrict__ hbuf, const float* __restrict__ w2,
                        const float* __restrict__ b2, const float* __restrict__ evsum,
                        float* __restrict__ out, int N)
{
    int gw = (blockIdx.x * blockDim.x + threadIdx.x) >> 5;
    int lane = threadIdx.x & 31;
    if (gw >= N) return;
    float2 v = *(const float2*)&hbuf[(size_t)gw * 64 + lane * 2];
    const float* wc = &w2[lane * 6];
    float a0 = v.x * wc[0] + v.y * wc[3];
    float a1 = v.x * wc[1] + v.y * wc[4];
    float a2 = v.x * wc[2] + v.y * wc[5];
    a0 = wsumf(a0); a1 = wsumf(a1); a2 = wsumf(a2);
    if (lane == 0) {
        float e0 = softplusf(a0 + b2[0]) + 1.f;
        float e1 = softplusf(a1 + b2[1]) + 1.f;
        float e2 = softplusf(a2 + b2[2]) + 1.f;
        out[(size_t)gw * 3 + 0] = (evsum[gw * 3 + 0] * 0.25f + e0) * 0.5f;
        out[(size_t)gw * 3 + 1] = (evsum[gw * 3 + 1] * 0.25f + e1) * 0.5f;
        out[(size_t)gw * 3 + 2] = (evsum[gw * 3 + 2] * 0.25f + e2) * 0.5f;
    }
}

// ---------------- LayerNorm + ELU ----------------
template <int F>
__global__ void k_ln_elu(const float* __restrict__ in, float* __restrict__ out,
                         const float* __restrict__ gam, const float* __restrict__ bet, int N)
{
    int gw = (blockIdx.x * blockDim.x + threadIdx.x) >> 5;
    int lane = threadIdx.x & 31;
    if (gw >= N) return;
    constexpr int R = F / 32;
    float v[R];
    const float* ir = &in[(size_t)gw * F];
#pragma unroll
    for (int r = 0; r < R; r++) v[r] = ir[lane + 32 * r];
    float s = 0.f;
#pragma unroll
    for (int r = 0; r < R; r++) s += v[r];
    s = wsumf(s);
    float mean = s * (1.f / F);
    float q = 0.f;
#pragma unroll
    for (int r = 0; r < R; r++) { float d = v[r] - mean; q = fmaf(d, d, q); }
    q = wsumf(q);
    float rstd = rsqrtf(q * (1.f / F) + 1e-5f);
    float* orow = &out[(size_t)gw * F];
#pragma unroll
    for (int r = 0; r < R; r++) {
        int j = lane + 32 * r;
        float y = (v[r] - mean) * rstd * gam[j] + bet[j];
        orow[j] = eluf(y);
    }
}

// ---------------- launch ----------------
extern "C" void kernel_launch(void* const* d_in, const int* in_sizes, int n_in,
                              void* d_out, int out_size)
{
    (void)in_sizes; (void)n_in; (void)out_size;

    const float* x        = (const float*)d_in[0];
    const int*   ei       = (const int*)  d_in[1];
    const float* W_heads  = (const float*)d_in[2];
    const float* a_heads  = (const float*)d_in[3];
    const float* ev1w_h   = (const float*)d_in[4];
    const float* ev1b_h   = (const float*)d_in[5];
    const float* ev2w_h   = (const float*)d_in[6];
    const float* ev2b_h   = (const float*)d_in[7];
    const float* agg_w    = (const float*)d_in[8];
    const float* agg_b    = (const float*)d_in[9];
    const float* ln1_g    = (const float*)d_in[10];
    const float* ln1_b    = (const float*)d_in[11];
    const float* W2       = (const float*)d_in[12];
    const float* a2       = (const float*)d_in[13];
    const float* ev1w2    = (const float*)d_in[14];
    const float* ev1b2    = (const float*)d_in[15];
    const float* ev2w2    = (const float*)d_in[16];
    const float* ev2b2    = (const float*)d_in[17];
    const float* ln2_g    = (const float*)d_in[18];
    const float* ln2_b    = (const float*)d_in[19];
    const float* res_w    = (const float*)d_in[20];
    const float* res_b    = (const float*)d_in[21];

    const int* src = ei;
    const int* tgt = ei + EE;

    float* out_x  = (float*)d_out;
    float* out_ev = (float*)d_out + (size_t)NN * DOUT;

    float *Wh, *xnew, *s1, *s2, *wbuf, *w2e, *hbuf, *evsum, *h1, *Wh2, *s1b, *s2b, *xnew2, *x2;
    __nv_bfloat16 *bt1hi, *bt1lo, *btahi, *btalo, *btehi, *btelo, *btw2hi, *btw2lo, *btrhi, *btrlo;
    cudaGetSymbolAddress((void**)&Wh,    g_Wh);
    cudaGetSymbolAddress((void**)&xnew,  g_xnew);
    cudaGetSymbolAddress((void**)&s1,    g_s1);
    cudaGetSymbolAddress((void**)&s2,    g_s2);
    cudaGetSymbolAddress((void**)&wbuf,  g_w);
    cudaGetSymbolAddress((void**)&w2e,   g_w2e);
    cudaGetSymbolAddress((void**)&hbuf,  g_hbuf);
    cudaGetSymbolAddress((void**)&evsum, g_evsum);
    cudaGetSymbolAddress((void**)&h1,    g_h1);
    cudaGetSymbolAddress((void**)&Wh2,   g_Wh2);
    cudaGetSymbolAddress((void**)&s1b,   g_s1b);
    cudaGetSymbolAddress((void**)&s2b,   g_s2b);
    cudaGetSymbolAddress((void**)&xnew2, g_xnew2);
    cudaGetSymbolAddress((void**)&x2,    g_x2);
    cudaGetSymbolAddress((void**)&bt1hi, g_bt1hi);
    cudaGetSymbolAddress((void**)&bt1lo, g_bt1lo);
    cudaGetSymbolAddress((void**)&btahi, g_btahi);
    cudaGetSymbolAddress((void**)&btalo, g_btalo);
    cudaGetSymbolAddress((void**)&btehi, g_btehi);
    cudaGetSymbolAddress((void**)&btelo, g_btelo);
    cudaGetSymbolAddress((void**)&btw2hi, g_btw2hi);
    cudaGetSymbolAddress((void**)&btw2lo, g_btw2lo);
    cudaGetSymbolAddress((void**)&btrhi, g_btrhi);
    cudaGetSymbolAddress((void**)&btrlo, g_btrlo);

    const int MB = (NN + 127) / 128;   // 235

    // 0) zero accumulators + transposed bf16-split weights
    k_init<<<2048, 256>>>();
    k_bt<<<(1024 * 768 + 255) / 256, 256>>>(W_heads, bt1hi, bt1lo, 768, 1024, 256, 768 * 256);
    k_bt<<<(256 * 1024 + 255) / 256, 256>>>(agg_w,  btahi, btalo, 1024, 256, 256, 0);
    k_bt<<<(512 * 256 + 255) / 256, 256>>>(ev1w_h, btehi, btelo, 256, 512, 128, 256 * 128);
    k_bt<<<(128 * 256 + 255) / 256, 256>>>(W2,     btw2hi, btw2lo, 256, 128, 128, 0);
    k_bt<<<(128 * 256 + 255) / 256, 256>>>(res_w,  btrhi, btrlo, 256, 128, 128, 0);

    // 1) Wh = x @ W_heads   [30000,768] x [768,1024]
    k_mma<0><<<dim3(8, MB), 256>>>(x, DIN, 0, 128, bt1hi, bt1lo,
                                   Wh, 1024, nullptr, nullptr, 0, NN, DIN);

    // 2) attention scalars + maxima, edge pass, softmax scale
    k_s1s2<<<(NN * NHEAD) / 8, 256>>>(Wh, NHEAD * DH, DH, NHEAD, a_heads, 2 * DH, s1, s2, NN, 0, 4);
    k_prepM<<<1, 8>>>(0, 0, 4, NHEAD);
    k_expsum<NHEAD><<<(EE + 255) / 256, 256>>>(src, tgt, s1, s2, wbuf, EE, NN, 0);
    k_finalize<<<1, 8>>>(0, NHEAD);

    // 3) scatter all heads
    k_scatter<NHEAD, DH><<<EE / 8, 256>>>(src, tgt, wbuf, Wh, NHEAD * DH, xnew, NHEAD * DH, EE, 0);

    // 4) evidence layer 1 (block-diagonal, relu) + fused head
    k_mma<1><<<dim3(4, MB), 256>>>(xnew, NHEAD * DH, DH, 128, btehi, btelo,
                                   hbuf, 512, ev1b_h, nullptr, 0, NN, DH);
    k_evid1<<<NN / 8, 256>>>(hbuf, ev2w_h, ev2b_h, evsum, NN);

    // 5) h1 = elu(LN(x_cat @ agg_w + agg_b))
    k_mma<0><<<dim3(2, MB), 256>>>(xnew, NHEAD * DH, 0, 128, btahi, btalo,
                                   h1, DH, agg_b, nullptr, 0, NN, NHEAD * DH);
    k_ln_elu<DH><<<NN / 8, 256>>>(h1, h1, ln1_g, ln1_b, NN);

    // 6) layer-2 GAT
    k_mma<0><<<dim3(1, MB), 256>>>(h1, DH, 0, 128, btw2hi, btw2lo,
                                   Wh2, DOUT, nullptr, nullptr, 0, NN, DH);
    k_s1s2<<<NN / 8, 256>>>(Wh2, DOUT, DOUT, 1, a2, 2 * DOUT, s1b, s2b, NN, 8, 9);
    k_prepM<<<1, 8>>>(4, 8, 9, 1);
    k_expsum<1><<<(EE + 255) / 256, 256>>>(src, tgt, s1b, s2b, w2e, EE, NN, 4);
    k_finalize<<<1, 8>>>(4, 1);
    k_scatter<1, DOUT><<<EE / 8, 256>>>(src, tgt, w2e, Wh2, DOUT, xnew2, DOUT, EE, 4);

    // 7) evidence layer 2 + final combine
    k_sgemm<1><<<dim3(1, MB), 256>>>(xnew2, DOUT, ev1w2, DOUT / 2, hbuf, DOUT / 2,
                                     ev1b2, NN, DOUT / 2, DOUT);
    k_evid2<<<NN / 8, 256>>>(hbuf, ev2w2, ev2b2, evsum, out_ev, NN);

    // 8) x2 = elu(LN(x_new2)); x_out = x2 + h1 @ res_w + res_b
    k_ln_elu<DOUT><<<NN / 8, 256>>>(xnew2, x2, ln2_g, ln2_b, NN);
    k_mma<2><<<dim3(1, MB), 256>>>(h1, DH, 0, 128, btrhi, btrlo,
                                   out_x, DOUT, res_b, x2, DOUT, NN, DH);
}

// round 9
// speedup vs baseline: 2.6302x; 1.2143x over previous
#include <cuda_runtime.h>
#include <cuda_bf16.h>
#include <math.h>
#include <stdint.h>

// ---------------- problem constants ----------------
#define NN   30000
#define EE   480000
#define DIN  768
#define DH   256    // HID
#define DOUT 128    // OUT
#define NHEAD 4
#define NCLS 3

// ---------------- scratch (static device memory; no allocations) ----------------
__device__ float    g_Wh   [(size_t)NN * (NHEAD * DH)];
__device__ float    g_xnew [(size_t)NN * (NHEAD * DH)];
__device__ float    g_s1   [NHEAD * NN];
__device__ float    g_s2   [NHEAD * NN];
__device__ float    g_w    [(size_t)NHEAD * EE];
__device__ float    g_w2e  [EE];
__device__ float    g_hbuf [(size_t)NN * 512];
__device__ float    g_evsum[NN * NCLS];
__device__ float    g_h1   [(size_t)NN * DH];
__device__ float    g_Wh2  [(size_t)NN * DOUT];
__device__ float    g_s1b  [NN];
__device__ float    g_s2b  [NN];
__device__ float    g_xnew2[(size_t)NN * DOUT];
__device__ float    g_x2   [(size_t)NN * DOUT];
__device__ unsigned g_maxenc[12];
__device__ float    g_M    [8];
__device__ double   g_sumexp[8];
__device__ float    g_invS  [8];

// CSR (edges grouped by tgt) — built once, used by both layers
__device__ int g_rowptr[NN + 1];
__device__ int g_cursor[NN];
__device__ int g_eidx  [EE];

// transposed + bf16-split weights (Bt[n][k], K-major)
__device__ __nv_bfloat16 g_bt1hi [1024 * 768], g_bt1lo [1024 * 768];   // W_heads
__device__ __nv_bfloat16 g_btahi [256 * 1024], g_btalo [256 * 1024];   // agg_w
__device__ __nv_bfloat16 g_btehi [512 * 256],  g_btelo [512 * 256];    // ev1w_heads
__device__ __nv_bfloat16 g_btw2hi[128 * 256],  g_btw2lo[128 * 256];    // W2
__device__ __nv_bfloat16 g_btrhi [128 * 256],  g_btrlo [128 * 256];    // res_w

// ---------------- helpers ----------------
__device__ __forceinline__ unsigned fenc(float f) {
    unsigned u = __float_as_uint(f);
    return (u & 0x80000000u) ? ~u : (u | 0x80000000u);
}
__device__ __forceinline__ float fdec(unsigned u) {
    return (u & 0x80000000u) ? __uint_as_float(u & 0x7fffffffu) : __uint_as_float(~u);
}
__device__ __forceinline__ float wsumf(float v) {
#pragma unroll
    for (int o = 16; o > 0; o >>= 1) v += __shfl_xor_sync(0xffffffffu, v, o);
    return v;
}
__device__ __forceinline__ float softplusf(float x) {
    return fmaxf(x, 0.f) + log1pf(expf(-fabsf(x)));
}
__device__ __forceinline__ float eluf(float x) {
    return x > 0.f ? x : expm1f(x);
}
__device__ __forceinline__ void bf16split(float x, __nv_bfloat16& hi, __nv_bfloat16& lo) {
    hi = __float2bfloat16(x);
    lo = __float2bfloat16(x - __bfloat162float(hi));
}

// mma.sync m16n8k16 bf16 (row.col), fp32 accumulate — compiles on plain sm_103.
__device__ __forceinline__ void mma_bf16(float* c, const uint32_t* a, const uint32_t* b) {
    asm volatile(
        "mma.sync.aligned.m16n8k16.row.col.f32.bf16.bf16.f32 "
        "{%0,%1,%2,%3}, {%4,%5,%6,%7}, {%8,%9}, {%0,%1,%2,%3};"
        : "+f"(c[0]), "+f"(c[1]), "+f"(c[2]), "+f"(c[3])
        : "r"(a[0]), "r"(a[1]), "r"(a[2]), "r"(a[3]), "r"(b[0]), "r"(b[1]));
}

// ---------------- init: zero CSR counters + softmax scalars ----------------
__global__ void k_init() {
    int i = blockIdx.x * blockDim.x + threadIdx.x;
    int stride = gridDim.x * blockDim.x;
    for (int j = i; j <= NN; j += stride) g_rowptr[j] = 0;
    if (i < 12) g_maxenc[i] = 0u;
    if (i < 8)  { g_sumexp[i] = 0.0; g_invS[i] = 0.f; g_M[i] = 0.f; }
}

// ---------------- CSR build ----------------
__global__ void k_hist(const int* __restrict__ tgt) {
    int e = blockIdx.x * blockDim.x + threadIdx.x;
    if (e < EE) atomicAdd(&g_rowptr[tgt[e] + 1], 1);
}

__global__ void k_scan() {
    __shared__ int part[1024];
    int tid = threadIdx.x;
    const int CH = (NN + 1023) / 1024;
    int beg = tid * CH;
    int end = beg + CH; if (end > NN) end = NN;
    int s = 0;
    for (int i = beg; i < end; i++) s += g_rowptr[i + 1];
    part[tid] = s;
    __syncthreads();
    for (int off = 1; off < 1024; off <<= 1) {
        int v = (tid >= off) ? part[tid - off] : 0;
        __syncthreads();
        part[tid] += v;
        __syncthreads();
    }
    int run = (tid > 0) ? part[tid - 1] : 0;
    for (int i = beg; i < end; i++) {
        int c = g_rowptr[i + 1];
        g_cursor[i] = run;       // start of node i
        run += c;
        g_rowptr[i + 1] = run;   // inclusive prefix
    }
    if (tid == 0) g_rowptr[0] = 0;
}

__global__ void k_fill(const int* __restrict__ tgt) {
    int e = blockIdx.x * blockDim.x + threadIdx.x;
    if (e < EE) {
        int p = atomicAdd(&g_cursor[tgt[e]], 1);
        g_eidx[p] = e;
    }
}

// ---------------- B transpose + bf16 split (one-time, tiny) ----------------
__global__ void k_bt(const float* __restrict__ src, __nv_bfloat16* __restrict__ bthi,
                     __nv_bfloat16* __restrict__ btlo, int K, int nTotal, int headN, int headStride)
{
    int idx = blockIdx.x * blockDim.x + threadIdx.x;
    if (idx >= nTotal * K) return;
    int n = idx / K, k = idx - n * K;
    int head = n / headN, nloc = n - head * headN;
    float v = src[(size_t)head * headStride + (size_t)k * headN + nloc];
    __nv_bfloat16 hi, lo;
    bf16split(v, hi, lo);
    bthi[idx] = hi;
    btlo[idx] = lo;
}

// ---------------- bf16-split tensor-core GEMM, double-buffered ----------------
// C[M, 128*gx] = A @ Bt^T ; A fp32 (split in load path), Bt pre-split bf16 [N,K] K-major.
// EPI: 0 = (+bias); 1 = relu(+bias); 2 = +bias +addend.
#define ASTR 40                 // smem row stride in bf16 elems
#define TILE_B 10240            // bytes per sub-tile (128*ASTR*2)
#define BUF_B  (4 * TILE_B)     // Ahi/Alo/Bhi/Blo
#define MMA_SMEM (2 * BUF_B)    // double buffer = 81920 B

template <int EPI>
__global__ __launch_bounds__(256, 1)
void k_mma(const float* __restrict__ A, int lda, int aHeadStep, int headN,
           const __nv_bfloat16* __restrict__ Bthi, const __nv_bfloat16* __restrict__ Btlo,
           float* __restrict__ C, int ldc,
           const float* __restrict__ bias,
           const float* __restrict__ addend, int ldadd,
           int M, int K)
{
    extern __shared__ __align__(16) char smraw[];

    const int tid = threadIdx.x;
    const int lane = tid & 31;
    const int wid = tid >> 5;
    const int warp_m = wid & 1;
    const int warp_n = wid >> 1;
    const int g  = lane >> 2;
    const int tg = lane & 3;

    const int m0 = blockIdx.y * 128;
    const int n0 = blockIdx.x * 128;
    const float* __restrict__ Ap = A + (size_t)(n0 / headN) * aHeadStep;

    float acc[4][4][4];
#pragma unroll
    for (int i = 0; i < 4; i++)
#pragma unroll
        for (int j = 0; j < 4; j++)
#pragma unroll
            for (int k = 0; k < 4; k++) acc[i][j][k] = 0.f;

    float4 ra[4];
    uint4  rbh[2], rbl[2];

    auto load_tiles = [&](int k0) {
#pragma unroll
        for (int i = 0; i < 4; i++) {
            int idx = tid + 256 * i;
            int row = idx >> 3, c4 = (idx & 7) << 2;
            int gm = m0 + row;
            ra[i] = (gm < M) ? *(const float4*)&Ap[(size_t)gm * lda + k0 + c4]
                             : make_float4(0.f, 0.f, 0.f, 0.f);
        }
#pragma unroll
        for (int i = 0; i < 2; i++) {
            int idx = tid + 256 * i;
            int row = idx >> 2, c8 = (idx & 3) << 3;
            size_t gi = (size_t)(n0 + row) * K + k0 + c8;
            rbh[i] = *(const uint4*)&Bthi[gi];
            rbl[i] = *(const uint4*)&Btlo[gi];
        }
    };
    auto store_tiles = [&](int s) {
        __nv_bfloat16* sAhi = (__nv_bfloat16*)(smraw + s * BUF_B);
        __nv_bfloat16* sAlo = (__nv_bfloat16*)(smraw + s * BUF_B + TILE_B);
        __nv_bfloat16* sBhi = (__nv_bfloat16*)(smraw + s * BUF_B + 2 * TILE_B);
        __nv_bfloat16* sBlo = (__nv_bfloat16*)(smraw + s * BUF_B + 3 * TILE_B);
#pragma unroll
        for (int i = 0; i < 4; i++) {
            int idx = tid + 256 * i;
            int row = idx >> 3, c4 = (idx & 7) << 2;
            __nv_bfloat16 hx, lx, hy, ly, hz, lz, hw, lw;
            bf16split(ra[i].x, hx, lx); bf16split(ra[i].y, hy, ly);
            bf16split(ra[i].z, hz, lz); bf16split(ra[i].w, hw, lw);
            int o = row * ASTR + c4;
            *(__nv_bfloat162*)&sAhi[o]     = __nv_bfloat162(hx, hy);
            *(__nv_bfloat162*)&sAhi[o + 2] = __nv_bfloat162(hz, hw);
            *(__nv_bfloat162*)&sAlo[o]     = __nv_bfloat162(lx, ly);
            *(__nv_bfloat162*)&sAlo[o + 2] = __nv_bfloat162(lz, lw);
        }
#pragma unroll
        for (int i = 0; i < 2; i++) {
            int idx = tid + 256 * i;
            int row = idx >> 2, c8 = (idx & 3) << 3;
            *(uint4*)&sBhi[row * ASTR + c8] = rbh[i];
            *(uint4*)&sBlo[row * ASTR + c8] = rbl[i];
        }
    };
    auto compute = [&](int s) {
        const __nv_bfloat16* sAhi = (const __nv_bfloat16*)(smraw + s * BUF_B);
        const __nv_bfloat16* sAlo = (const __nv_bfloat16*)(smraw + s * BUF_B + TILE_B);
        const __nv_bfloat16* sBhi = (const __nv_bfloat16*)(smraw + s * BUF_B + 2 * TILE_B);
        const __nv_bfloat16* sBlo = (const __nv_bfloat16*)(smraw + s * BUF_B + 3 * TILE_B);
#pragma unroll
        for (int kc = 0; kc < 32; kc += 16) {
            uint32_t ah[4][4], al[4][4];
#pragma unroll
            for (int mt = 0; mt < 4; mt++) {
                int base = (warp_m * 64 + mt * 16 + g) * ASTR + kc + tg * 2;
                ah[mt][0] = *(const uint32_t*)&sAhi[base];
                ah[mt][1] = *(const uint32_t*)&sAhi[base + 8 * ASTR];
                ah[mt][2] = *(const uint32_t*)&sAhi[base + 8];
                ah[mt][3] = *(const uint32_t*)&sAhi[base + 8 * ASTR + 8];
                al[mt][0] = *(const uint32_t*)&sAlo[base];
                al[mt][1] = *(const uint32_t*)&sAlo[base + 8 * ASTR];
                al[mt][2] = *(const uint32_t*)&sAlo[base + 8];
                al[mt][3] = *(const uint32_t*)&sAlo[base + 8 * ASTR + 8];
            }
            uint32_t bh[4][2], bl[4][2];
#pragma unroll
            for (int nt = 0; nt < 4; nt++) {
                int base = (warp_n * 32 + nt * 8 + g) * ASTR + kc + tg * 2;
                bh[nt][0] = *(const uint32_t*)&sBhi[base];
                bh[nt][1] = *(const uint32_t*)&sBhi[base + 8];
                bl[nt][0] = *(const uint32_t*)&sBlo[base];
                bl[nt][1] = *(const uint32_t*)&sBlo[base + 8];
            }
#pragma unroll
            for (int mt = 0; mt < 4; mt++)
#pragma unroll
                for (int nt = 0; nt < 4; nt++) {
                    mma_bf16(acc[mt][nt], ah[mt], bh[nt]);
                    mma_bf16(acc[mt][nt], ah[mt], bl[nt]);
                    mma_bf16(acc[mt][nt], al[mt], bh[nt]);
                }
        }
    };

    const int T = K / 32;
    load_tiles(0);
    store_tiles(0);
    __syncthreads();
    for (int t = 1; t < T; t++) {
        load_tiles(t * 32);
        compute((t - 1) & 1);
        store_tiles(t & 1);
        __syncthreads();
    }
    compute((T - 1) & 1);

    // epilogue
#pragma unroll
    for (int mt = 0; mt < 4; mt++) {
        int r0 = m0 + warp_m * 64 + mt * 16 + g;
#pragma unroll
        for (int nt = 0; nt < 4; nt++) {
            int gc = n0 + warp_n * 32 + nt * 8 + tg * 2;
            float2 v01 = make_float2(acc[mt][nt][0], acc[mt][nt][1]);
            float2 v23 = make_float2(acc[mt][nt][2], acc[mt][nt][3]);
            if (bias) {
                float2 b = *(const float2*)&bias[gc];
                v01.x += b.x; v01.y += b.y;
                v23.x += b.x; v23.y += b.y;
            }
            if (EPI == 1) {
                v01.x = fmaxf(v01.x, 0.f); v01.y = fmaxf(v01.y, 0.f);
                v23.x = fmaxf(v23.x, 0.f); v23.y = fmaxf(v23.y, 0.f);
            }
            if (r0 < M) {
                if (EPI == 2) {
                    float2 adx = *(const float2*)&addend[(size_t)r0 * ldadd + gc];
                    v01.x += adx.x; v01.y += adx.y;
                }
                *(float2*)&C[(size_t)r0 * ldc + gc] = v01;
            }
            if (r0 + 8 < M) {
                if (EPI == 2) {
                    float2 adx = *(const float2*)&addend[(size_t)(r0 + 8) * ldadd + gc];
                    v23.x += adx.x; v23.y += adx.y;
                }
                *(float2*)&C[(size_t)(r0 + 8) * ldc + gc] = v23;
            }
        }
    }
}

// ---------------- fp32 SGEMM (small evidence-2 GEMM only) ----------------
#define BM 128
#define BN 128
#define BKK 16
template <int EPI>
__global__ __launch_bounds__(256, 2)
void k_sgemm(const float* __restrict__ A, int lda,
             const float* __restrict__ B, int ldb,
             float* __restrict__ C, int ldc,
             const float* __restrict__ bias,
             int M, int N, int K)
{
    __shared__ float As[BKK][BM + 4];
    __shared__ float Bs[BKK][BN];
    const int tid = threadIdx.x;
    const int m0 = blockIdx.y * BM;
    const int n0 = blockIdx.x * BN;
    const int tm = tid >> 4, tn = tid & 15;
    const int a_kk = tid & 15, a_m0 = tid >> 4;
    const int b_kk0 = tid >> 5, b_nb = (tid & 31) << 2;

    float acc[8][8];
#pragma unroll
    for (int i = 0; i < 8; i++)
#pragma unroll
        for (int j = 0; j < 8; j++) acc[i][j] = 0.f;

    float ra[8]; float4 rb[2];
    auto load_tiles = [&](int k0) {
#pragma unroll
        for (int i = 0; i < 8; i++) {
            int gm = m0 + a_m0 + 16 * i;
            ra[i] = (gm < M) ? A[(size_t)gm * lda + (k0 + a_kk)] : 0.f;
        }
#pragma unroll
        for (int i = 0; i < 2; i++) {
            int kk = b_kk0 + 8 * i;
            int gn = n0 + b_nb;
            float4 v = make_float4(0.f, 0.f, 0.f, 0.f);
            const float* bp = &B[(size_t)(k0 + kk) * ldb + b_nb];
            if (gn + 3 < N) v = *(const float4*)bp;
            else {
                if (gn     < N) v.x = bp[0];
                if (gn + 1 < N) v.y = bp[1];
                if (gn + 2 < N) v.z = bp[2];
            }
            rb[i] = v;
        }
    };
    auto store_tiles = [&]() {
#pragma unroll
        for (int i = 0; i < 8; i++) As[a_kk][a_m0 + 16 * i] = ra[i];
#pragma unroll
        for (int i = 0; i < 2; i++) *(float4*)&Bs[b_kk0 + 8 * i][b_nb] = rb[i];
    };
    auto compute = [&]() {
#pragma unroll
        for (int kk = 0; kk < BKK; kk++) {
            float a[8], b[8];
#pragma unroll
            for (int i = 0; i < 8; i++) a[i] = As[kk][tm * 8 + i];
#pragma unroll
            for (int j = 0; j < 8; j++) b[j] = Bs[kk][tn * 8 + j];
#pragma unroll
            for (int i = 0; i < 8; i++)
#pragma unroll
                for (int j = 0; j < 8; j++) acc[i][j] = fmaf(a[i], b[j], acc[i][j]);
        }
    };
    load_tiles(0); store_tiles(); __syncthreads();
    for (int k0 = BKK; k0 < K; k0 += BKK) {
        load_tiles(k0); compute(); __syncthreads(); store_tiles(); __syncthreads();
    }
    compute();
#pragma unroll
    for (int i = 0; i < 8; i++) {
        int gm = m0 + tm * 8 + i;
        if (gm < M) {
#pragma unroll
            for (int j = 0; j < 8; j++) {
                int gn = n0 + tn * 8 + j;
                if (gn < N) {
                    float v = acc[i][j];
                    if (bias) v += bias[gn];
                    if (EPI == 1) v = fmaxf(v, 0.f);
                    C[(size_t)gm * ldc + gn] = v;
                }
            }
        }
    }
}

// ---------------- attention projections + node maxima ----------------
__global__ void k_s1s2(const float* __restrict__ Wh, int ld, int F, int nh,
                       const float* __restrict__ a, int aStride,
                       float* __restrict__ s1, float* __restrict__ s2, int N,
                       int slot1, int slot2)
{
    int gw = (blockIdx.x * blockDim.x + threadIdx.x) >> 5;
    int lane = threadIdx.x & 31;
    if (gw >= N * nh) return;
    int node = gw / nh;
    int h = gw - node * nh;
    const float* wr = &Wh[(size_t)node * ld + h * F];
    const float* ah = &a[(size_t)h * aStride];
    float p1 = 0.f, p2 = 0.f;
    for (int j = lane; j < F; j += 32) {
        float x = wr[j];
        p1 = fmaf(x, ah[j], p1);
        p2 = fmaf(x, ah[F + j], p2);
    }
    p1 = wsumf(p1); p2 = wsumf(p2);
    if (lane == 0) {
        s1[(size_t)h * N + node] = p1;
        s2[(size_t)h * N + node] = p2;
        atomicMax(&g_maxenc[slot1 + h], fenc(p1));
        atomicMax(&g_maxenc[slot2 + h], fenc(p2));
    }
}

__global__ void k_prepM(int slot, int slot1, int slot2, int n)
{
    int i = threadIdx.x;
    if (i < n) {
        float l = fdec(g_maxenc[slot1 + i]) + fdec(g_maxenc[slot2 + i]);
        g_M[slot + i] = (l > 0.f) ? l : 0.2f * l;
    }
}

template <int NH>
__global__ void k_expsum(const int* __restrict__ src, const int* __restrict__ tgt,
                         const float* __restrict__ s1, const float* __restrict__ s2,
                         float* __restrict__ w, int E, int N, int slot)
{
    int e = blockIdx.x * blockDim.x + threadIdx.x;
    bool ok = (e < E);
    int s = 0, t = 0;
    if (ok) { s = src[e]; t = tgt[e]; }
    float sv[NH];
#pragma unroll
    for (int h = 0; h < NH; h++) {
        float v = 0.f;
        if (ok) {
            float l = s1[(size_t)h * N + s] + s2[(size_t)h * N + t];
            l = (l > 0.f) ? l : 0.2f * l;
            v = expf(l - g_M[slot + h]);
            w[(size_t)h * E + e] = v;
        }
        sv[h] = v;
    }
    __shared__ float red[256];
#pragma unroll
    for (int h = 0; h < NH; h++) {
        red[threadIdx.x] = sv[h];
        __syncthreads();
        for (int sft = 128; sft > 0; sft >>= 1) {
            if (threadIdx.x < sft) red[threadIdx.x] += red[threadIdx.x + sft];
            __syncthreads();
        }
        if (threadIdx.x == 0) atomicAdd(&g_sumexp[slot + h], (double)red[0]);
        __syncthreads();
    }
}

__global__ void k_finalize(int slot0, int n)
{
    int i = threadIdx.x;
    if (i < n) g_invS[slot0 + i] = (float)(1.0 / g_sumexp[slot0 + i]);
}

// ---------------- CSR gather: x_new[n] = invS * sum_{e: tgt=n} w_e * Wh[src_e] ----------------
// F=1024 (layer 1, 4 heads): one 256-thread block per node, float4 per thread.
__global__ __launch_bounds__(256, 8)
void k_gather1024(const int* __restrict__ src, const float* __restrict__ w,
                  const float* __restrict__ Wh, float* __restrict__ xnew, int slot0)
{
    int node = blockIdx.x;
    int tid = threadIdx.x;
    int head = tid >> 6;                     // 64 threads per head (256 feats)
    int col = tid * 4;
    const float* wh = &w[(size_t)head * EE];

    int p = g_rowptr[node];
    const int end = g_rowptr[node + 1];

    int s_cur = 0; float c_cur = 0.f;
    if (p < end) { int e = g_eidx[p]; s_cur = src[e]; c_cur = wh[e]; }

    float4 acc = make_float4(0.f, 0.f, 0.f, 0.f);
    while (p < end) {
        int s_nxt = 0; float c_nxt = 0.f;
        if (p + 1 < end) { int e = g_eidx[p + 1]; s_nxt = src[e]; c_nxt = wh[e]; }
        float4 v = *(const float4*)&Wh[(size_t)s_cur * 1024 + col];
        acc.x = fmaf(c_cur, v.x, acc.x);
        acc.y = fmaf(c_cur, v.y, acc.y);
        acc.z = fmaf(c_cur, v.z, acc.z);
        acc.w = fmaf(c_cur, v.w, acc.w);
        s_cur = s_nxt; c_cur = c_nxt; p++;
    }
    float inv = g_invS[slot0 + head];
    acc.x *= inv; acc.y *= inv; acc.z *= inv; acc.w *= inv;
    *(float4*)&xnew[(size_t)node * 1024 + col] = acc;
}

// F=128 (layer 2): one warp per node.
__global__ __launch_bounds__(256, 8)
void k_gather128(const int* __restrict__ src, const float* __restrict__ w,
                 const float* __restrict__ Wh, float* __restrict__ xnew, int slot)
{
    int node = (blockIdx.x * blockDim.x + threadIdx.x) >> 5;
    int lane = threadIdx.x & 31;
    if (node >= NN) return;
    int col = lane * 4;

    int p = g_rowptr[node];
    const int end = g_rowptr[node + 1];

    int s_cur = 0; float c_cur = 0.f;
    if (p < end) { int e = g_eidx[p]; s_cur = src[e]; c_cur = w[e]; }

    float4 acc = make_float4(0.f, 0.f, 0.f, 0.f);
    while (p < end) {
        int s_nxt = 0; float c_nxt = 0.f;
        if (p + 1 < end) { int e = g_eidx[p + 1]; s_nxt = src[e]; c_nxt = w[e]; }
        float4 v = *(const float4*)&Wh[(size_t)s_cur * 128 + col];
        acc.x = fmaf(c_cur, v.x, acc.x);
        acc.y = fmaf(c_cur, v.y, acc.y);
        acc.z = fmaf(c_cur, v.z, acc.z);
        acc.w = fmaf(c_cur, v.w, acc.w);
        s_cur = s_nxt; c_cur = c_nxt; p++;
    }
    float inv = g_invS[slot];
    acc.x *= inv; acc.y *= inv; acc.z *= inv; acc.w *= inv;
    *(float4*)&xnew[(size_t)node * 128 + col] = acc;
}

// ---------------- evidence heads ----------------
__global__ void k_evid1(const float* __restrict__ hbuf, const float* __restrict__ w2,
                        const float* __restrict__ b2, float* __restrict__ evsum, int N)
{
    int gw = (blockIdx.x * blockDim.x + threadIdx.x) >> 5;
    int lane = threadIdx.x & 31;
    if (gw >= N) return;
    float e0 = 0.f, e1 = 0.f, e2 = 0.f;
#pragma unroll
    for (int h = 0; h < NHEAD; h++) {
        float4 v = *(const float4*)&hbuf[(size_t)gw * 512 + h * 128 + lane * 4];
        const float* wc = &w2[h * 384 + lane * 12];
        float a0 = v.x * wc[0] + v.y * wc[3] + v.z * wc[6] + v.w * wc[9];
        float a1 = v.x * wc[1] + v.y * wc[4] + v.z * wc[7] + v.w * wc[10];
        float a2 = v.x * wc[2] + v.y * wc[5] + v.z * wc[8] + v.w * wc[11];
        a0 = wsumf(a0); a1 = wsumf(a1); a2 = wsumf(a2);
        e0 += softplusf(a0 + b2[h * 3 + 0]) + 1.f;
        e1 += softplusf(a1 + b2[h * 3 + 1]) + 1.f;
        e2 += softplusf(a2 + b2[h * 3 + 2]) + 1.f;
    }
    if (lane == 0) {
        evsum[gw * 3 + 0] = e0; evsum[gw * 3 + 1] = e1; evsum[gw * 3 + 2] = e2;
    }
}

__global__ void k_evid2(const float* __restrict__ hbuf, const float* __restrict__ w2,
                        const float* __restrict__ b2, const float* __restrict__ evsum,
                        float* __restrict__ out, int N)
{
    int gw = (blockIdx.x * blockDim.x + threadIdx.x) >> 5;
    int lane = threadIdx.x & 31;
    if (gw >= N) return;
    float2 v = *(const float2*)&hbuf[(size_t)gw * 64 + lane * 2];
    const float* wc = &w2[lane * 6];
    float a0 = v.x * wc[0] + v.y * wc[3];
    float a1 = v.x * wc[1] + v.y * wc[4];
    float a2 = v.x * wc[2] + v.y * wc[5];
    a0 = wsumf(a0); a1 = wsumf(a1); a2 = wsumf(a2);
    if (lane == 0) {
        float e0 = softplusf(a0 + b2[0]) + 1.f;
        float e1 = softplusf(a1 + b2[1]) + 1.f;
        float e2 = softplusf(a2 + b2[2]) + 1.f;
        out[(size_t)gw * 3 + 0] = (evsum[gw * 3 + 0] * 0.25f + e0) * 0.5f;
        out[(size_t)gw * 3 + 1] = (evsum[gw * 3 + 1] * 0.25f + e1) * 0.5f;
        out[(size_t)gw * 3 + 2] = (evsum[gw * 3 + 2] * 0.25f + e2) * 0.5f;
    }
}

// ---------------- LayerNorm + ELU ----------------
template <int F>
__global__ void k_ln_elu(const float* __restrict__ in, float* __restrict__ out,
                         const float* __restrict__ gam, const float* __restrict__ bet, int N)
{
    int gw = (blockIdx.x * blockDim.x + threadIdx.x) >> 5;
    int lane = threadIdx.x & 31;
    if (gw >= N) return;
    constexpr int R = F / 32;
    float v[R];
    const float* ir = &in[(size_t)gw * F];
#pragma unroll
    for (int r = 0; r < R; r++) v[r] = ir[lane + 32 * r];
    float s = 0.f;
#pragma unroll
    for (int r = 0; r < R; r++) s += v[r];
    s = wsumf(s);
    float mean = s * (1.f / F);
    float q = 0.f;
#pragma unroll
    for (int r = 0; r < R; r++) { float d = v[r] - mean; q = fmaf(d, d, q); }
    q = wsumf(q);
    float rstd = rsqrtf(q * (1.f / F) + 1e-5f);
    float* orow = &out[(size_t)gw * F];
#pragma unroll
    for (int r = 0; r < R; r++) {
        int j = lane + 32 * r;
        float y = (v[r] - mean) * rstd * gam[j] + bet[j];
        orow[j] = eluf(y);
    }
}

// ---------------- launch ----------------
extern "C" void kernel_launch(void* const* d_in, const int* in_sizes, int n_in,
                              void* d_out, int out_size)
{
    (void)in_sizes; (void)n_in; (void)out_size;

    const float* x        = (const float*)d_in[0];
    const int*   ei       = (const int*)  d_in[1];
    const float* W_heads  = (const float*)d_in[2];
    const float* a_heads  = (const float*)d_in[3];
    const float* ev1w_h   = (const float*)d_in[4];
    const float* ev1b_h   = (const float*)d_in[5];
    const float* ev2w_h   = (const float*)d_in[6];
    const float* ev2b_h   = (const float*)d_in[7];
    const float* agg_w    = (const float*)d_in[8];
    const float* agg_b    = (const float*)d_in[9];
    const float* ln1_g    = (const float*)d_in[10];
    const float* ln1_b    = (const float*)d_in[11];
    const float* W2       = (const float*)d_in[12];
    const float* a2       = (const float*)d_in[13];
    const float* ev1w2    = (const float*)d_in[14];
    const float* ev1b2    = (const float*)d_in[15];
    const float* ev2w2    = (const float*)d_in[16];
    const float* ev2b2    = (const float*)d_in[17];
    const float* ln2_g    = (const float*)d_in[18];
    const float* ln2_b    = (const float*)d_in[19];
    const float* res_w    = (const float*)d_in[20];
    const float* res_b    = (const float*)d_in[21];

    const int* src = ei;
    const int* tgt = ei + EE;

    float* out_x  = (float*)d_out;
    float* out_ev = (float*)d_out + (size_t)NN * DOUT;

    float *Wh, *xnew, *s1, *s2, *wbuf, *w2e, *hbuf, *evsum, *h1, *Wh2, *s1b, *s2b, *xnew2, *x2;
    __nv_bfloat16 *bt1hi, *bt1lo, *btahi, *btalo, *btehi, *btelo, *btw2hi, *btw2lo, *btrhi, *btrlo;
    cudaGetSymbolAddress((void**)&Wh,    g_Wh);
    cudaGetSymbolAddress((void**)&xnew,  g_xnew);
    cudaGetSymbolAddress((void**)&s1,    g_s1);
    cudaGetSymbolAddress((void**)&s2,    g_s2);
    cudaGetSymbolAddress((void**)&wbuf,  g_w);
    cudaGetSymbolAddress((void**)&w2e,   g_w2e);
    cudaGetSymbolAddress((void**)&hbuf,  g_hbuf);
    cudaGetSymbolAddress((void**)&evsum, g_evsum);
    cudaGetSymbolAddress((void**)&h1,    g_h1);
    cudaGetSymbolAddress((void**)&Wh2,   g_Wh2);
    cudaGetSymbolAddress((void**)&s1b,   g_s1b);
    cudaGetSymbolAddress((void**)&s2b,   g_s2b);
    cudaGetSymbolAddress((void**)&xnew2, g_xnew2);
    cudaGetSymbolAddress((void**)&x2,    g_x2);
    cudaGetSymbolAddress((void**)&bt1hi, g_bt1hi);
    cudaGetSymbolAddress((void**)&bt1lo, g_bt1lo);
    cudaGetSymbolAddress((void**)&btahi, g_btahi);
    cudaGetSymbolAddress((void**)&btalo, g_btalo);
    cudaGetSymbolAddress((void**)&btehi, g_btehi);
    cudaGetSymbolAddress((void**)&btelo, g_btelo);
    cudaGetSymbolAddress((void**)&btw2hi, g_btw2hi);
    cudaGetSymbolAddress((void**)&btw2lo, g_btw2lo);
    cudaGetSymbolAddress((void**)&btrhi, g_btrhi);
    cudaGetSymbolAddress((void**)&btrlo, g_btrlo);

    cudaFuncSetAttribute(k_mma<0>, cudaFuncAttributeMaxDynamicSharedMemorySize, MMA_SMEM);
    cudaFuncSetAttribute(k_mma<1>, cudaFuncAttributeMaxDynamicSharedMemorySize, MMA_SMEM);
    cudaFuncSetAttribute(k_mma<2>, cudaFuncAttributeMaxDynamicSharedMemorySize, MMA_SMEM);

    const int MB = (NN + 127) / 128;   // 235

    // 0) zero CSR counters + scalars; weight transposes; CSR build
    k_init<<<128, 256>>>();
    k_bt<<<(1024 * 768 + 255) / 256, 256>>>(W_heads, bt1hi, bt1lo, 768, 1024, 256, 768 * 256);
    k_bt<<<(256 * 1024 + 255) / 256, 256>>>(agg_w,  btahi, btalo, 1024, 256, 256, 0);
    k_bt<<<(512 * 256 + 255) / 256, 256>>>(ev1w_h, btehi, btelo, 256, 512, 128, 256 * 128);
    k_bt<<<(128 * 256 + 255) / 256, 256>>>(W2,     btw2hi, btw2lo, 256, 128, 128, 0);
    k_bt<<<(128 * 256 + 255) / 256, 256>>>(res_w,  btrhi, btrlo, 256, 128, 128, 0);
    k_hist<<<(EE + 255) / 256, 256>>>(tgt);
    k_scan<<<1, 1024>>>();
    k_fill<<<(EE + 255) / 256, 256>>>(tgt);

    // 1) Wh = x @ W_heads   [30000,768] x [768,1024]
    k_mma<0><<<dim3(8, MB), 256, MMA_SMEM>>>(x, DIN, 0, 128, bt1hi, bt1lo,
                                             Wh, 1024, nullptr, nullptr, 0, NN, DIN);

    // 2) attention scalars + maxima, edge pass, softmax scale
    k_s1s2<<<(NN * NHEAD) / 8, 256>>>(Wh, NHEAD * DH, DH, NHEAD, a_heads, 2 * DH, s1, s2, NN, 0, 4);
    k_prepM<<<1, 8>>>(0, 0, 4, NHEAD);
    k_expsum<NHEAD><<<(EE + 255) / 256, 256>>>(src, tgt, s1, s2, wbuf, EE, NN, 0);
    k_finalize<<<1, 8>>>(0, NHEAD);

    // 3) CSR gather (all heads)
    k_gather1024<<<NN, 256>>>(src, wbuf, Wh, xnew, 0);

    // 4) evidence layer 1 (block-diagonal, relu) + fused head
    k_mma<1><<<dim3(4, MB), 256, MMA_SMEM>>>(xnew, NHEAD * DH, DH, 128, btehi, btelo,
                                             hbuf, 512, ev1b_h, nullptr, 0, NN, DH);
    k_evid1<<<NN / 8, 256>>>(hbuf, ev2w_h, ev2b_h, evsum, NN);

    // 5) h1 = elu(LN(x_cat @ agg_w + agg_b))
    k_mma<0><<<dim3(2, MB), 256, MMA_SMEM>>>(xnew, NHEAD * DH, 0, 128, btahi, btalo,
                                             h1, DH, agg_b, nullptr, 0, NN, NHEAD * DH);
    k_ln_elu<DH><<<NN / 8, 256>>>(h1, h1, ln1_g, ln1_b, NN);

    // 6) layer-2 GAT
    k_mma<0><<<dim3(1, MB), 256, MMA_SMEM>>>(h1, DH, 0, 128, btw2hi, btw2lo,
                                             Wh2, DOUT, nullptr, nullptr, 0, NN, DH);
    k_s1s2<<<NN / 8, 256>>>(Wh2, DOUT, DOUT, 1, a2, 2 * DOUT, s1b, s2b, NN, 8, 9);
    k_prepM<<<1, 8>>>(4, 8, 9, 1);
    k_expsum<1><<<(EE + 255) / 256, 256>>>(src, tgt, s1b, s2b, w2e, EE, NN, 4);
    k_finalize<<<1, 8>>>(4, 1);
    k_gather128<<<(NN * 32 + 255) / 256, 256>>>(src, w2e, Wh2, xnew2, 4);

    // 7) evidence layer 2 + final combine
    k_sgemm<1><<<dim3(1, MB), 256>>>(xnew2, DOUT, ev1w2, DOUT / 2, hbuf, DOUT / 2,
                                     ev1b2, NN, DOUT / 2, DOUT);
    k_evid2<<<NN / 8, 256>>>(hbuf, ev2w2, ev2b2, evsum, out_ev, NN);

    // 8) x2 = elu(LN(x_new2)); x_out = x2 + h1 @ res_w + res_b
    k_ln_elu<DOUT><<<NN / 8, 256>>>(xnew2, x2, ln2_g, ln2_b, NN);
    k_mma<2><<<dim3(1, MB), 256, MMA_SMEM>>>(h1, DH, 0, 128, btrhi, btrlo,
                                             out_x, DOUT, res_b, x2, DOUT, NN, DH);
}